// round 7
// baseline (speedup 1.0000x reference)
#include <cuda_runtime.h>
#include <math.h>
#include <float.h>

typedef unsigned int u32;

static constexpr int NB = 8, N1 = 4096, N2 = 2048, N3 = 512, KNN = 32;

// ---------------- scratch ----------------
__device__ int   g_idx1[NB * N1 * KNN];
__device__ int   g_cnt1[NB * N1];
__device__ float g_a1  [NB * N1 * 64];
__device__ float g_x1  [NB * N1 * 64];
__device__ int   g_fi1 [NB * N2];
__device__ float g_pos2[NB * N2 * 3];
__device__ float g_x2g [NB * N2 * 64];
__device__ float g_a2  [NB * N2 * 128];
__device__ int   g_idx2[NB * N2 * KNN];
__device__ int   g_cnt2[NB * N2];
__device__ float g_x2  [NB * N2 * 128];
__device__ int   g_fi2 [NB * N3];
__device__ float g_pos3[NB * N3 * 3];
__device__ float g_x3g [NB * N3 * 128];
__device__ float g_a3  [NB * N3 * 256];
__device__ int   g_idx3[NB * N3 * KNN];
__device__ int   g_cnt3[NB * N3];
__device__ float g_x3  [NB * N3 * 256];

// ---------------- tf32 helpers ----------------
__device__ __forceinline__ u32 f2tf32(float f) {
    u32 r; asm("cvt.rna.tf32.f32 %0,%1;" : "=r"(r) : "f"(f)); return r;
}
__device__ __forceinline__ void mma_tf32(float* d, const u32* A, u32 b0, u32 b1) {
    asm("mma.sync.aligned.m16n8k8.row.col.f32.tf32.tf32.f32 "
        "{%0,%1,%2,%3},{%4,%5,%6,%7},{%8,%9},{%0,%1,%2,%3};"
        : "+f"(d[0]), "+f"(d[1]), "+f"(d[2]), "+f"(d[3])
        : "r"(A[0]), "r"(A[1]), "r"(A[2]), "r"(A[3]), "r"(b0), "r"(b1));
}

// ---------------- per-node a_j = [x_j, pos_j] @ W1 + b1 ----------------
template <int CINX, int CHID>
__global__ void __launch_bounds__(256)
node_pre_kernel(const float* __restrict__ x, const float* __restrict__ pos,
                const float* __restrict__ W1, const float* __restrict__ b1,
                float* __restrict__ a, int nNodes)
{
    int tid = blockIdx.x * 256 + threadIdx.x;
    if (tid >= nNodes * CHID) return;
    int node = tid / CHID, c = tid - node * CHID;
    float acc = b1[c];
    if (CINX > 0) {
        const float* xr = x + (size_t)node * CINX;
#pragma unroll 4
        for (int f = 0; f < CINX; ++f)
            acc = fmaf(xr[f], W1[f * CHID + c], acc);
    }
    const float* pr = pos + (size_t)node * 3;
    acc = fmaf(pr[0], W1[(CINX + 0) * CHID + c], acc);
    acc = fmaf(pr[1], W1[(CINX + 1) * CHID + c], acc);
    acc = fmaf(pr[2], W1[(CINX + 2) * CHID + c], acc);
    a[tid] = acc;
}

// ---------------- KNN (512 threads/block), register top-32 ----------------
__device__ void knn_dev(const float* __restrict__ pb, int N, float r2v,
                        int* __restrict__ oidx, int* __restrict__ ocnt,
                        int qb, float4* sj)
{
    const int t = threadIdx.x;
    const int i = qb * 512 + t;
    const float xi = pb[i * 3 + 0], yi = pb[i * 3 + 1], zi = pb[i * 3 + 2];
    const float sqi = __fadd_rn(__fadd_rn(__fmul_rn(xi, xi), __fmul_rn(yi, yi)),
                                __fmul_rn(zi, zi));
    const float m2x = -2.f * xi, m2y = -2.f * yi, m2z = -2.f * zi;

    float bd[KNN];
    int   bi_[KNN];
#pragma unroll
    for (int k = 0; k < KNN; ++k) { bd[k] = FLT_MAX; bi_[k] = 0; }
    float worst = FLT_MAX;

    for (int t0 = 0; t0 < N; t0 += 512) {
        __syncthreads();
        {
            int j = t0 + t;
            float x = pb[j * 3 + 0], y = pb[j * 3 + 1], z = pb[j * 3 + 2];
            float sq = __fadd_rn(__fadd_rn(__fmul_rn(x, x), __fmul_rn(y, y)),
                                 __fmul_rn(z, z));
            sj[t] = make_float4(x, y, z, sq);
        }
        __syncthreads();
#pragma unroll 2
        for (int jj = 0; jj < 512; ++jj) {
            float4 q = sj[jj];
            float d2 = sqi + fmaf(m2x, q.x, fmaf(m2y, q.y, fmaf(m2z, q.z, q.w)));
            int j = t0 + jj;
            if (d2 <= r2v && d2 < worst && j != i) {
#pragma unroll
                for (int k = KNN - 1; k > 0; --k) {
                    if (bd[k - 1] > d2)  { bd[k] = bd[k - 1]; bi_[k] = bi_[k - 1]; }
                    else if (bd[k] > d2) { bd[k] = d2;        bi_[k] = j; }
                }
                if (bd[0] > d2)          { bd[0] = d2;        bi_[0] = j; }
                worst = bd[KNN - 1];
            }
        }
    }
    int cnt = 0;
#pragma unroll
    for (int k = 0; k < KNN; ++k) cnt += (bd[k] <= r2v) ? 1 : 0;
    ocnt[i] = cnt;
    const int base = i * KNN;
#pragma unroll
    for (int k = 0; k < KNN; ++k) oidx[base + k] = bi_[k];
}

// ---------------- FPS (512 threads): single barrier per iteration --------
template <int P>
__device__ void fps_dev(const float* __restrict__ pb, int nS,
                        int* __restrict__ out, float* sm)
{
    const int N = P * 512;
    float* spos = sm;
    u32*  svb = (u32*)(sm + N * 3);   // [2][16]
    int*  si  = (int*)(svb + 32);     // [2][16]
    const int t = threadIdx.x, w = t >> 5, l = t & 31;

    for (int e = t; e < N * 3; e += 512) spos[e] = pb[e];
    __syncthreads();

    float px[P], py[P], pz[P], mind[P];
    const float x0 = spos[0], y0 = spos[1], z0 = spos[2];
    float bv = -1.f; int bidx = 0x7fffffff;
#pragma unroll
    for (int p = 0; p < P; ++p) {
        int i = t + p * 512;
        px[p] = spos[i * 3 + 0]; py[p] = spos[i * 3 + 1]; pz[p] = spos[i * 3 + 2];
        float dx = px[p] - x0, dy = py[p] - y0, dz = pz[p] - z0;
        mind[p] = __fadd_rn(__fadd_rn(__fmul_rn(dx, dx), __fmul_rn(dy, dy)),
                            __fmul_rn(dz, dz));
        if (mind[p] > bv) { bv = mind[p]; bidx = i; }
    }
    if (t == 0) out[0] = 0;

    int par = 0;
    for (int s = 1; s < nS; ++s) {
        u32 vb = __float_as_uint(bv);                 // mind >= 0 -> monotone
        u32 m  = __reduce_max_sync(0xffffffffu, vb);
        u32 cand = (vb == m) ? (u32)bidx : 0xffffffffu;
        u32 wi = __reduce_min_sync(0xffffffffu, cand);
        if (l == 0) { svb[par * 16 + w] = m; si[par * 16 + w] = (int)wi; }
        __syncthreads();
        u32 v2 = (l < 16) ? svb[par * 16 + l] : 0u;
        u32 i2 = (l < 16) ? (u32)si[par * 16 + l] : 0xffffffffu;
        u32 m2 = __reduce_max_sync(0xffffffffu, v2);
        u32 c2 = (v2 == m2 && l < 16) ? i2 : 0xffffffffu;
        u32 gi = __reduce_min_sync(0xffffffffu, c2);
        if (t == 0) out[s] = (int)gi;
        const float cx = spos[gi * 3 + 0];
        const float cy = spos[gi * 3 + 1];
        const float cz = spos[gi * 3 + 2];
        par ^= 1;
        bv = -1.f; bidx = 0x7fffffff;
#pragma unroll
        for (int p = 0; p < P; ++p) {
            float dx = px[p] - cx, dy = py[p] - cy, dz = pz[p] - cz;
            float d = __fadd_rn(__fadd_rn(__fmul_rn(dx, dx), __fmul_rn(dy, dy)),
                                __fmul_rn(dz, dz));
            mind[p] = fminf(mind[p], d);
            if (mind[p] > bv) { bv = mind[p]; bidx = t + p * 512; }
        }
    }
}

// ---------------- fused KNN + FPS launch ----------------
template <int P>
__global__ void __launch_bounds__(512, 1)
mega_kernel(const float* __restrict__ pos, float r2v,
            int* __restrict__ oidx, int* __restrict__ ocnt,
            int nS, int* __restrict__ fi)
{
    extern __shared__ char sm[];
    const int N = P * 512;
    if (blockIdx.x < NB) {
        fps_dev<P>(pos + (size_t)blockIdx.x * N * 3, nS,
                   fi + blockIdx.x * nS, (float*)sm);
    } else {
        int kb = blockIdx.x - NB;
        int b = kb % NB, qb = kb / NB;
        knn_dev(pos + (size_t)b * N * 3, N, r2v,
                oidx + (size_t)b * N * KNN, ocnt + b * N, qb, (float4*)sm);
    }
}

__global__ void __launch_bounds__(512, 1)
knn_kernel(const float* __restrict__ pos, int N, float r2v,
           int* __restrict__ oidx, int* __restrict__ ocnt)
{
    extern __shared__ char sm[];
    int b = blockIdx.x % NB, qb = blockIdx.x / NB;
    knn_dev(pos + (size_t)b * N * 3, N, r2v,
            oidx + (size_t)b * N * KNN, ocnt + b * N, qb, (float4*)sm);
}

// ---------------- gather after FPS ----------------
__global__ void gather_kernel(const float* __restrict__ xin,
                              const float* __restrict__ posin,
                              const int* __restrict__ fi,
                              float* __restrict__ xo, float* __restrict__ poso,
                              int Nin, int Nout, int C)
{
    const int tid = blockIdx.x * blockDim.x + threadIdx.x;
    const int stride = gridDim.x * blockDim.x;
    const int totX = NB * Nout * C;
    for (int e = tid; e < totX; e += stride) {
        int c = e % C, m = (e / C) % Nout, b = e / (C * Nout);
        int j = fi[b * Nout + m];
        xo[e] = xin[((size_t)b * Nin + j) * C + c];
    }
    const int totP = NB * Nout * 3;
    for (int e = tid; e < totP; e += stride) {
        int d = e % 3, m = (e / 3) % Nout, b = e / (3 * Nout);
        int j = fi[b * Nout + m];
        poso[e] = posin[((size_t)b * Nin + j) * 3 + d];
    }
}

// ---------------- PointNetConv phase-2 on tensor cores (tf32 mma) --------
// Per point: D = h[32 x CHID] @ W2[CHID x COUT]; masked max over rows.
// Group of COUT threads per point; warp w covers 32 output cols (4 N-tiles).
template <int CHID, int COUT>
__global__ void __launch_bounds__(256)
conv_mma_kernel(const float* __restrict__ a, const float* __restrict__ pos,
                const int* __restrict__ kidx, const int* __restrict__ kcnt,
                const float* __restrict__ W1p, const float* __restrict__ W2,
                const float* __restrict__ b2, float* __restrict__ xout, int N)
{
    constexpr int CHIDP = CHID + 4;
    constexpr int PPB = 256 / COUT;              // points per block
    constexpr int KT = CHID / 8;                 // k-tiles
    constexpr int GSZ = 32 * CHIDP + CHID;
    extern __shared__ float smem[];
    const int tg = threadIdx.x / COUT;
    const int t  = threadIdx.x % COUT;
    float* sh1 = smem + tg * GSZ;                // [32][CHIDP]
    float* scv = sh1 + 32 * CHIDP;               // [CHID]
    __shared__ int   sidx[PPB][KNN];
    __shared__ float spi[PPB][3];
    __shared__ int   scnt[PPB];

    const int b = blockIdx.y;
    const int i = blockIdx.x * PPB + tg;

    if (t < KNN) sidx[tg][t] = kidx[((size_t)b * N + i) * KNN + t];
    if (t == 0)  scnt[tg] = kcnt[b * N + i];
    if (t < 3)   spi[tg][t] = pos[((size_t)b * N + i) * 3 + t];
    __syncthreads();
    const float p0 = spi[tg][0], p1 = spi[tg][1], p2 = spi[tg][2];
    for (int c = t; c < CHID; c += COUT)
        scv[c] = fmaf(p2, W1p[2 * CHID + c],
                      fmaf(p1, W1p[CHID + c], p0 * W1p[c]));
    __syncthreads();

    // h = relu(a_j - c_i) into sh1
    const float* ab = a + (size_t)b * N * CHID;
    constexpr int V = CHID / 4;
    for (int e = t; e < 32 * V; e += COUT) {
        int k = e / V, c4 = e - k * V;
        int j = sidx[tg][k];
        float4 av = *(const float4*)&ab[(size_t)j * CHID + c4 * 4];
        float4 cv = *(const float4*)&scv[c4 * 4];
        float4 h;
        h.x = fmaxf(av.x - cv.x, 0.f);
        h.y = fmaxf(av.y - cv.y, 0.f);
        h.z = fmaxf(av.z - cv.z, 0.f);
        h.w = fmaxf(av.w - cv.w, 0.f);
        *(float4*)&sh1[k * CHIDP + c4 * 4] = h;
    }
    __syncthreads();

    // MMA: warp w handles cols [w*32, w*32+32)
    const int lane = t & 31;
    const int w = t >> 5;
    const int q = lane >> 2, kk = lane & 3;

    float d[2][4][4];
#pragma unroll
    for (int m = 0; m < 2; ++m)
#pragma unroll
        for (int n = 0; n < 4; ++n)
#pragma unroll
            for (int r = 0; r < 4; ++r) d[m][n][r] = 0.f;

    for (int kt = 0; kt < KT; ++kt) {
        u32 A[2][4];
#pragma unroll
        for (int m = 0; m < 2; ++m) {
            const float* base = &sh1[(m * 16 + q) * CHIDP + kt * 8 + kk];
            A[m][0] = f2tf32(base[0]);
            A[m][1] = f2tf32(base[8 * CHIDP]);
            A[m][2] = f2tf32(base[4]);
            A[m][3] = f2tf32(base[8 * CHIDP + 4]);
        }
#pragma unroll
        for (int n = 0; n < 4; ++n) {
            int c = w * 32 + n * 8 + q;
            u32 B0 = f2tf32(W2[(kt * 8 + kk) * COUT + c]);
            u32 B1 = f2tf32(W2[(kt * 8 + kk + 4) * COUT + c]);
            mma_tf32(d[0][n], A[0], B0, B1);
            mma_tf32(d[1][n], A[1], B0, B1);
        }
    }

    // epilogue: masked max over 32 rows, cross-lane reduce, bias + relu
    const int cnt = scnt[tg];
#pragma unroll
    for (int n = 0; n < 4; ++n) {
        float v0 = -FLT_MAX, v1 = -FLT_MAX;
#pragma unroll
        for (int m = 0; m < 2; ++m) {
            int r0 = m * 16 + q, r1 = r0 + 8;
            if (r0 < cnt) { v0 = fmaxf(v0, d[m][n][0]); v1 = fmaxf(v1, d[m][n][1]); }
            if (r1 < cnt) { v0 = fmaxf(v0, d[m][n][2]); v1 = fmaxf(v1, d[m][n][3]); }
        }
        v0 = fmaxf(v0, __shfl_xor_sync(0xffffffffu, v0, 4));
        v1 = fmaxf(v1, __shfl_xor_sync(0xffffffffu, v1, 4));
        v0 = fmaxf(v0, __shfl_xor_sync(0xffffffffu, v0, 8));
        v1 = fmaxf(v1, __shfl_xor_sync(0xffffffffu, v1, 8));
        v0 = fmaxf(v0, __shfl_xor_sync(0xffffffffu, v0, 16));
        v1 = fmaxf(v1, __shfl_xor_sync(0xffffffffu, v1, 16));
        if (lane < 4) {
            int c = w * 32 + n * 8 + lane * 2;
            float o0 = (cnt > 0) ? fmaxf(v0 + b2[c], 0.f) : 0.f;
            float o1 = (cnt > 0) ? fmaxf(v1 + b2[c + 1], 0.f) : 0.f;
            xout[((size_t)b * N + i) * COUT + c]     = o0;
            xout[((size_t)b * N + i) * COUT + c + 1] = o1;
        }
    }
}

// ---------------- head ----------------
__global__ void head_kernel(const float* __restrict__ x3,
                            const float* __restrict__ Wc1, const float* __restrict__ bc1,
                            const float* __restrict__ Wc2, const float* __restrict__ bc2,
                            const float* __restrict__ Wc3, const float* __restrict__ bc3,
                            const float* __restrict__ Wd1, const float* __restrict__ bd1,
                            const float* __restrict__ Wd2, const float* __restrict__ bd2,
                            float* __restrict__ out)
{
    __shared__ float sf[256], sh[256], sh2[256], slog[40], sd[2];
    const int b = blockIdx.x, t = threadIdx.x;

    float m = -FLT_MAX;
    for (int n = 0; n < N3; ++n)
        m = fmaxf(m, x3[((size_t)b * N3 + n) * 256 + t]);
    sf[t] = m;
    __syncthreads();

    float a = bc1[t];
    for (int c = 0; c < 256; ++c) a = fmaf(sf[c], Wc1[c * 256 + t], a);
    sh[t] = fmaxf(a, 0.f);
    __syncthreads();

    a = bc2[t];
    for (int c = 0; c < 256; ++c) a = fmaf(sh[c], Wc2[c * 256 + t], a);
    sh2[t] = fmaxf(a, 0.f);
    __syncthreads();

    if (t < 40) {
        float l = bc3[t];
        for (int c = 0; c < 256; ++c) l = fmaf(sh2[c], Wc3[c * 40 + t], l);
        slog[t] = l;
    }
    float a2 = bd1[t];
    for (int c = 0; c < 256; ++c) a2 = fmaf(sf[c], Wd1[c * 256 + t], a2);
    a2 = fmaxf(a2, 0.f);
    __syncthreads();
    sh[t] = a2;
    __syncthreads();
    if (t < 2) {
        float l = bd2[t];
        for (int c = 0; c < 256; ++c) l = fmaf(sh[c], Wd2[c * 2 + t], l);
        sd[t] = l;
    }
    __syncthreads();

    if (t < 40) {
        float mx = -FLT_MAX;
        for (int j = 0; j < 40; ++j) mx = fmaxf(mx, slog[j]);
        float se = 0.f;
        for (int j = 0; j < 40; ++j) se += expf(slog[j] - mx);
        out[b * 40 + t] = slog[t] - mx - logf(se);
    }
    if (t < 2) {
        float mx = fmaxf(sd[0], sd[1]);
        float se = expf(sd[0] - mx) + expf(sd[1] - mx);
        out[NB * 40 + b * 2 + t] = sd[t] - mx - logf(se);
    }
}

// ---------------- launch ----------------
extern "C" void kernel_launch(void* const* d_in, const int* in_sizes, int n_in,
                              void* d_out, int out_size)
{
    const float* pos = (const float*)d_in[0];
    const float* W1a = (const float*)d_in[1];  const float* b1a = (const float*)d_in[2];
    const float* W1b = (const float*)d_in[3];  const float* b1b = (const float*)d_in[4];
    const float* W2a = (const float*)d_in[5];  const float* b2a = (const float*)d_in[6];
    const float* W2b = (const float*)d_in[7];  const float* b2b = (const float*)d_in[8];
    const float* W3a = (const float*)d_in[9];  const float* b3a = (const float*)d_in[10];
    const float* W3b = (const float*)d_in[11]; const float* b3b = (const float*)d_in[12];
    const float* Wc1 = (const float*)d_in[13]; const float* bc1 = (const float*)d_in[14];
    const float* Wc2 = (const float*)d_in[15]; const float* bc2 = (const float*)d_in[16];
    const float* Wc3 = (const float*)d_in[17]; const float* bc3 = (const float*)d_in[18];
    const float* Wd1 = (const float*)d_in[19]; const float* bd1 = (const float*)d_in[20];
    const float* Wd2 = (const float*)d_in[21]; const float* bd2 = (const float*)d_in[22];
    float* out = (float*)d_out;

    void *p_idx1, *p_cnt1, *p_a1, *p_x1, *p_fi1, *p_pos2, *p_x2g, *p_a2,
         *p_idx2, *p_cnt2, *p_x2, *p_fi2, *p_pos3, *p_x3g, *p_a3,
         *p_idx3, *p_cnt3, *p_x3;
    cudaGetSymbolAddress(&p_idx1, g_idx1);
    cudaGetSymbolAddress(&p_cnt1, g_cnt1);
    cudaGetSymbolAddress(&p_a1,   g_a1);
    cudaGetSymbolAddress(&p_x1,   g_x1);
    cudaGetSymbolAddress(&p_fi1,  g_fi1);
    cudaGetSymbolAddress(&p_pos2, g_pos2);
    cudaGetSymbolAddress(&p_x2g,  g_x2g);
    cudaGetSymbolAddress(&p_a2,   g_a2);
    cudaGetSymbolAddress(&p_idx2, g_idx2);
    cudaGetSymbolAddress(&p_cnt2, g_cnt2);
    cudaGetSymbolAddress(&p_x2,   g_x2);
    cudaGetSymbolAddress(&p_fi2,  g_fi2);
    cudaGetSymbolAddress(&p_pos3, g_pos3);
    cudaGetSymbolAddress(&p_x3g,  g_x3g);
    cudaGetSymbolAddress(&p_a3,   g_a3);
    cudaGetSymbolAddress(&p_idx3, g_idx3);
    cudaGetSymbolAddress(&p_cnt3, g_cnt3);
    cudaGetSymbolAddress(&p_x3,   g_x3);

    const int smMega1 = N1 * 12 + 256;            // 49408
    const int smMega2 = N2 * 12 + 256;            // 24832
    const int smKnn3  = 512 * 16;                 // 8192
    const int shc1 = 4 * (32 * (64 + 4)  + 64)  * 4;   // 35840
    const int shc2 = 2 * (32 * (128 + 4) + 128) * 4;   // 34816
    const int shc3 = 1 * (32 * (256 + 4) + 256) * 4;   // 34304
    cudaFuncSetAttribute(mega_kernel<8>,
                         cudaFuncAttributeMaxDynamicSharedMemorySize, 50176);

    const float r1 = 0.2f, r2 = 0.4f, r3 = 1.0f;

    // level 1
    node_pre_kernel<0, 64><<<(NB * N1 * 64) / 256, 256>>>(
        nullptr, pos, W1a, b1a, (float*)p_a1, NB * N1);
    mega_kernel<8><<<NB + (N1 / 512) * NB, 512, smMega1>>>(
        pos, r1 * r1, (int*)p_idx1, (int*)p_cnt1, N2, (int*)p_fi1);
    conv_mma_kernel<64, 64><<<dim3(N1 / 4, NB), 256, shc1>>>(
        (float*)p_a1, pos, (int*)p_idx1, (int*)p_cnt1,
        W1a, W1b, b1b, (float*)p_x1, N1);
    gather_kernel<<<256, 256>>>((float*)p_x1, pos, (int*)p_fi1,
                                (float*)p_x2g, (float*)p_pos2, N1, N2, 64);

    // level 2
    node_pre_kernel<64, 128><<<(NB * N2 * 128) / 256, 256>>>(
        (float*)p_x2g, (float*)p_pos2, W2a, b2a, (float*)p_a2, NB * N2);
    mega_kernel<4><<<NB + (N2 / 512) * NB, 512, smMega2>>>(
        (float*)p_pos2, r2 * r2, (int*)p_idx2, (int*)p_cnt2, N3, (int*)p_fi2);
    conv_mma_kernel<128, 128><<<dim3(N2 / 2, NB), 256, shc2>>>(
        (float*)p_a2, (float*)p_pos2, (int*)p_idx2, (int*)p_cnt2,
        W2a + 64 * 128, W2b, b2b, (float*)p_x2, N2);
    gather_kernel<<<256, 256>>>((float*)p_x2, (float*)p_pos2, (int*)p_fi2,
                                (float*)p_x3g, (float*)p_pos3, N2, N3, 128);

    // level 3
    node_pre_kernel<128, 256><<<(NB * N3 * 256) / 256, 256>>>(
        (float*)p_x3g, (float*)p_pos3, W3a, b3a, (float*)p_a3, NB * N3);
    knn_kernel<<<(N3 / 512) * NB, 512, smKnn3>>>(
        (float*)p_pos3, N3, r3 * r3, (int*)p_idx3, (int*)p_cnt3);
    conv_mma_kernel<256, 256><<<dim3(N3, NB), 256, shc3>>>(
        (float*)p_a3, (float*)p_pos3, (int*)p_idx3, (int*)p_cnt3,
        W3a + 128 * 256, W3b, b3b, (float*)p_x3, N3);

    // head
    head_kernel<<<NB, 256>>>((float*)p_x3, Wc1, bc1, Wc2, bc2, Wc3, bc3,
                             Wd1, bd1, Wd2, bd2, out);

    (void)in_sizes; (void)n_in; (void)out_size;
}

// round 8
// speedup vs baseline: 1.2245x; 1.2245x over previous
#include <cuda_runtime.h>
#include <math.h>
#include <float.h>

typedef unsigned int u32;

static constexpr int NB = 8, N1 = 4096, N2 = 2048, N3 = 512, KNN = 32;

// ---------------- scratch ----------------
__device__ int   g_idx1[NB * N1 * KNN];
__device__ int   g_cnt1[NB * N1];
__device__ float g_a1  [NB * N1 * 64];
__device__ float g_x1  [NB * N1 * 64];
__device__ int   g_fi1 [NB * N2];
__device__ float g_pos2[NB * N2 * 3];
__device__ float g_x2g [NB * N2 * 64];
__device__ float g_a2  [NB * N2 * 128];
__device__ int   g_idx2[NB * N2 * KNN];
__device__ int   g_cnt2[NB * N2];
__device__ float g_x2  [NB * N2 * 128];
__device__ int   g_fi2 [NB * N3];
__device__ float g_pos3[NB * N3 * 3];
__device__ float g_x3g [NB * N3 * 128];
__device__ float g_a3  [NB * N3 * 256];
__device__ int   g_idx3[NB * N3 * KNN];
__device__ int   g_cnt3[NB * N3];
__device__ float g_x3  [NB * N3 * 256];
__device__ int   g_perm1[NB * N1];
__device__ int   g_perm2[NB * N2];
__device__ int   g_perm3[NB * N3];

// ---------------- spatial counting sort (query coherence for KNN) --------
// Order is irrelevant to results (each query's output depends only on its own
// scan); binning only makes warp lanes spatially adjacent.
template <int NBIN>
__global__ void __launch_bounds__(256)
binsort_kernel(const float* __restrict__ pos, int N, int* __restrict__ perm)
{
    constexpr int B3 = NBIN * NBIN * NBIN;
    __shared__ int hist[B3];
    __shared__ int offs[B3];
    const int b = blockIdx.x, t = threadIdx.x;
    const float* pb = pos + (size_t)b * N * 3;

    for (int e = t; e < B3; e += 256) hist[e] = 0;
    __syncthreads();
    for (int i = t; i < N; i += 256) {
        int ix = min(NBIN - 1, max(0, (int)(pb[i * 3 + 0] * NBIN)));
        int iy = min(NBIN - 1, max(0, (int)(pb[i * 3 + 1] * NBIN)));
        int iz = min(NBIN - 1, max(0, (int)(pb[i * 3 + 2] * NBIN)));
        atomicAdd(&hist[(ix * NBIN + iy) * NBIN + iz], 1);
    }
    __syncthreads();
    if (t == 0) {
        int acc = 0;
        for (int k = 0; k < B3; ++k) { offs[k] = acc; acc += hist[k]; }
    }
    __syncthreads();
    for (int e = t; e < B3; e += 256) hist[e] = 0;
    __syncthreads();
    for (int i = t; i < N; i += 256) {
        int ix = min(NBIN - 1, max(0, (int)(pb[i * 3 + 0] * NBIN)));
        int iy = min(NBIN - 1, max(0, (int)(pb[i * 3 + 1] * NBIN)));
        int iz = min(NBIN - 1, max(0, (int)(pb[i * 3 + 2] * NBIN)));
        int key = (ix * NBIN + iy) * NBIN + iz;
        int r = offs[key] + atomicAdd(&hist[key], 1);
        perm[b * N + r] = i;
    }
}

// ---------------- per-node a_j = [x_j, pos_j] @ W1 + b1 ----------------
template <int CINX, int CHID>
__global__ void __launch_bounds__(256)
node_pre_kernel(const float* __restrict__ x, const float* __restrict__ pos,
                const float* __restrict__ W1, const float* __restrict__ b1,
                float* __restrict__ a, int nNodes)
{
    int tid = blockIdx.x * 256 + threadIdx.x;
    if (tid >= nNodes * CHID) return;
    int node = tid / CHID, c = tid - node * CHID;
    float acc = b1[c];
    if (CINX > 0) {
        const float* xr = x + (size_t)node * CINX;
#pragma unroll 4
        for (int f = 0; f < CINX; ++f)
            acc = fmaf(xr[f], W1[f * CHID + c], acc);
    }
    const float* pr = pos + (size_t)node * 3;
    acc = fmaf(pr[0], W1[(CINX + 0) * CHID + c], acc);
    acc = fmaf(pr[1], W1[(CINX + 1) * CHID + c], acc);
    acc = fmaf(pr[2], W1[(CINX + 2) * CHID + c], acc);
    a[tid] = acc;
}

// ---------------- KNN (256 thr), register top-32, bin-coherent queries ----
__device__ void knn_dev(const float* __restrict__ pb, int N, float r2v,
                        int* __restrict__ oidx, int* __restrict__ ocnt,
                        int qb, const int* __restrict__ perm, float4* sj)
{
    const int t = threadIdx.x;
    const int i = perm[qb * 256 + t];          // spatially-coherent query
    const float xi = pb[i * 3 + 0], yi = pb[i * 3 + 1], zi = pb[i * 3 + 2];
    const float sqi = __fadd_rn(__fadd_rn(__fmul_rn(xi, xi), __fmul_rn(yi, yi)),
                                __fmul_rn(zi, zi));
    const float m2x = -2.f * xi, m2y = -2.f * yi, m2z = -2.f * zi;

    float bd[KNN];
    int   bi_[KNN];
#pragma unroll
    for (int k = 0; k < KNN; ++k) { bd[k] = FLT_MAX; bi_[k] = 0; }
    float worst = FLT_MAX;

    for (int t0 = 0; t0 < N; t0 += 256) {
        __syncthreads();
        {
            int j = t0 + t;
            float x = pb[j * 3 + 0], y = pb[j * 3 + 1], z = pb[j * 3 + 2];
            float sq = __fadd_rn(__fadd_rn(__fmul_rn(x, x), __fmul_rn(y, y)),
                                 __fmul_rn(z, z));
            sj[t] = make_float4(x, y, z, sq);
        }
        __syncthreads();
#pragma unroll 2
        for (int jj = 0; jj < 256; ++jj) {
            float4 q = sj[jj];
            float d2 = sqi + fmaf(m2x, q.x, fmaf(m2y, q.y, fmaf(m2z, q.z, q.w)));
            int j = t0 + jj;
            if (d2 <= r2v && d2 < worst && j != i) {
#pragma unroll
                for (int k = KNN - 1; k > 0; --k) {
                    if (bd[k - 1] > d2)  { bd[k] = bd[k - 1]; bi_[k] = bi_[k - 1]; }
                    else if (bd[k] > d2) { bd[k] = d2;        bi_[k] = j; }
                }
                if (bd[0] > d2)          { bd[0] = d2;        bi_[0] = j; }
                worst = bd[KNN - 1];
            }
        }
    }
    int cnt = 0;
#pragma unroll
    for (int k = 0; k < KNN; ++k) cnt += (bd[k] <= r2v) ? 1 : 0;
    ocnt[i] = cnt;
    const int base = i * KNN;
#pragma unroll
    for (int k = 0; k < KNN; ++k) oidx[base + k] = bi_[k];
}

// ---------------- FPS (256 threads): single barrier per iteration --------
template <int P>
__device__ void fps_dev(const float* __restrict__ pb, int nS,
                        int* __restrict__ out, float* sm)
{
    const int N = P * 256;
    float* spos = sm;
    u32*  svb = (u32*)(sm + N * 3);   // [2][8]
    int*  si  = (int*)(svb + 16);     // [2][8]
    const int t = threadIdx.x, w = t >> 5, l = t & 31;

    for (int e = t; e < N * 3; e += 256) spos[e] = pb[e];
    __syncthreads();

    float px[P], py[P], pz[P], mind[P];
    const float x0 = spos[0], y0 = spos[1], z0 = spos[2];
    float bv = -1.f; int bidx = 0x7fffffff;
#pragma unroll
    for (int p = 0; p < P; ++p) {
        int i = t + p * 256;
        px[p] = spos[i * 3 + 0]; py[p] = spos[i * 3 + 1]; pz[p] = spos[i * 3 + 2];
        float dx = px[p] - x0, dy = py[p] - y0, dz = pz[p] - z0;
        mind[p] = __fadd_rn(__fadd_rn(__fmul_rn(dx, dx), __fmul_rn(dy, dy)),
                            __fmul_rn(dz, dz));
        if (mind[p] > bv) { bv = mind[p]; bidx = i; }
    }
    if (t == 0) out[0] = 0;

    int par = 0;
    for (int s = 1; s < nS; ++s) {
        u32 vb = __float_as_uint(bv);                 // mind >= 0 -> monotone
        u32 m  = __reduce_max_sync(0xffffffffu, vb);
        u32 cand = (vb == m) ? (u32)bidx : 0xffffffffu;
        u32 wi = __reduce_min_sync(0xffffffffu, cand);
        if (l == 0) { svb[par * 8 + w] = m; si[par * 8 + w] = (int)wi; }
        __syncthreads();
        u32 v2 = (l < 8) ? svb[par * 8 + l] : 0u;
        u32 i2 = (l < 8) ? (u32)si[par * 8 + l] : 0xffffffffu;
        u32 m2 = __reduce_max_sync(0xffffffffu, v2);
        u32 c2 = (v2 == m2 && l < 8) ? i2 : 0xffffffffu;
        u32 gi = __reduce_min_sync(0xffffffffu, c2);
        if (t == 0) out[s] = (int)gi;
        const float cx = spos[gi * 3 + 0];
        const float cy = spos[gi * 3 + 1];
        const float cz = spos[gi * 3 + 2];
        par ^= 1;
        bv = -1.f; bidx = 0x7fffffff;
#pragma unroll
        for (int p = 0; p < P; ++p) {
            float dx = px[p] - cx, dy = py[p] - cy, dz = pz[p] - cz;
            float d = __fadd_rn(__fadd_rn(__fmul_rn(dx, dx), __fmul_rn(dy, dy)),
                                __fmul_rn(dz, dz));
            mind[p] = fminf(mind[p], d);
            if (mind[p] > bv) { bv = mind[p]; bidx = t + p * 256; }
        }
    }
}

// ---------------- fused KNN + FPS launch (1 block/SM allowed) ----------
template <int P>
__global__ void __launch_bounds__(256, 1)
mega_kernel(const float* __restrict__ pos, float r2v,
            int* __restrict__ oidx, int* __restrict__ ocnt,
            int nS, int* __restrict__ fi, const int* __restrict__ perm)
{
    extern __shared__ char sm[];
    const int N = P * 256;
    if (blockIdx.x < NB) {
        fps_dev<P>(pos + (size_t)blockIdx.x * N * 3, nS,
                   fi + blockIdx.x * nS, (float*)sm);
    } else {
        int kb = blockIdx.x - NB;
        int b = kb % NB, qb = kb / NB;
        knn_dev(pos + (size_t)b * N * 3, N, r2v,
                oidx + (size_t)b * N * KNN, ocnt + b * N, qb,
                perm + b * N, (float4*)sm);
    }
}

__global__ void __launch_bounds__(256, 1)
knn_kernel(const float* __restrict__ pos, int N, float r2v,
           int* __restrict__ oidx, int* __restrict__ ocnt,
           const int* __restrict__ perm)
{
    extern __shared__ char sm[];
    int b = blockIdx.x % NB, qb = blockIdx.x / NB;
    knn_dev(pos + (size_t)b * N * 3, N, r2v,
            oidx + (size_t)b * N * KNN, ocnt + b * N, qb,
            perm + b * N, (float4*)sm);
}

// ---------------- gather after FPS ----------------
__global__ void gather_kernel(const float* __restrict__ xin,
                              const float* __restrict__ posin,
                              const int* __restrict__ fi,
                              float* __restrict__ xo, float* __restrict__ poso,
                              int Nin, int Nout, int C)
{
    const int tid = blockIdx.x * blockDim.x + threadIdx.x;
    const int stride = gridDim.x * blockDim.x;
    const int totX = NB * Nout * C;
    for (int e = tid; e < totX; e += stride) {
        int c = e % C, m = (e / C) % Nout, b = e / (C * Nout);
        int j = fi[b * Nout + m];
        xo[e] = xin[((size_t)b * Nin + j) * C + c];
    }
    const int totP = NB * Nout * 3;
    for (int e = tid; e < totP; e += stride) {
        int d = e % 3, m = (e / 3) % Nout, b = e / (3 * Nout);
        int j = fi[b * Nout + m];
        poso[e] = posin[((size_t)b * Nin + j) * 3 + d];
    }
}

// ---------------- PointNetConv (decomposed), TP points per 256-thr block --
template <int CHID, int COUT, int TP>
__global__ void __launch_bounds__(COUT * TP)
conv_kernel(const float* __restrict__ a, const float* __restrict__ pos,
            const int* __restrict__ kidx, const int* __restrict__ kcnt,
            const float* __restrict__ W1p, const float* __restrict__ W2,
            const float* __restrict__ b2, float* __restrict__ xout, int N)
{
    constexpr int CHIDP = CHID + 4;              // padded (bank-safe)
    constexpr int GSZ = 32 * CHIDP + CHID;       // floats per group
    extern __shared__ float smem[];
    const int tg = threadIdx.x / COUT;           // group -> point
    const int t  = threadIdx.x % COUT;
    float* sh1 = smem + tg * GSZ;                // [32][CHIDP]
    float* scv = sh1 + 32 * CHIDP;               // [CHID]
    __shared__ int   sidx[TP][KNN];
    __shared__ float spi[TP][3];
    __shared__ int   scnt[TP];

    const int b = blockIdx.y;
    const int i = blockIdx.x * TP + tg;

    if (t < KNN) sidx[tg][t] = kidx[((size_t)b * N + i) * KNN + t];
    if (t == 0)  scnt[tg] = kcnt[b * N + i];
    if (t < 3)   spi[tg][t] = pos[((size_t)b * N + i) * 3 + t];
    __syncthreads();
    const int cnt = scnt[tg];
    const float p0 = spi[tg][0], p1 = spi[tg][1], p2 = spi[tg][2];
    for (int c = t; c < CHID; c += COUT)
        scv[c] = fmaf(p2, W1p[2 * CHID + c],
                      fmaf(p1, W1p[CHID + c], p0 * W1p[c]));
    __syncthreads();

    // gather h = relu(a_j - c_i) for 32 neighbor slots (coalesced float4)
    const float* ab = a + (size_t)b * N * CHID;
    constexpr int V = CHID / 4;
    for (int e = t; e < 32 * V; e += COUT) {
        int k = e / V, c4 = e - k * V;
        int j = sidx[tg][k];
        float4 av = *(const float4*)&ab[(size_t)j * CHID + c4 * 4];
        float4 cv = *(const float4*)&scv[c4 * 4];
        float4 h;
        h.x = fmaxf(av.x - cv.x, 0.f);
        h.y = fmaxf(av.y - cv.y, 0.f);
        h.z = fmaxf(av.z - cv.z, 0.f);
        h.w = fmaxf(av.w - cv.w, 0.f);
        *(float4*)&sh1[k * CHIDP + c4 * 4] = h;
    }
    __syncthreads();

    // phase 2: acc = h @ W2; masked max over valid k
    float mv[8];
#pragma unroll
    for (int c = 0; c < 8; ++c) mv[c] = -FLT_MAX;
    constexpr int OG = COUT / 8;
    const int o0 = (t % OG) * 8;
    const int kg = t / OG;
    {
        const int k0 = kg * 4;
        float acc[8][4];
#pragma unroll
        for (int k = 0; k < 4; ++k) {
#pragma unroll
            for (int c = 0; c < 8; ++c) acc[c][k] = 0.f;
        }
#pragma unroll 2
        for (int cc = 0; cc < CHID; ++cc) {
            float4 wa = *(const float4*)&W2[cc * COUT + o0];
            float4 wb = *(const float4*)&W2[cc * COUT + o0 + 4];
#pragma unroll
            for (int k = 0; k < 4; ++k) {
                float s = sh1[(k0 + k) * CHIDP + cc];
                acc[0][k] = fmaf(s, wa.x, acc[0][k]);
                acc[1][k] = fmaf(s, wa.y, acc[1][k]);
                acc[2][k] = fmaf(s, wa.z, acc[2][k]);
                acc[3][k] = fmaf(s, wa.w, acc[3][k]);
                acc[4][k] = fmaf(s, wb.x, acc[4][k]);
                acc[5][k] = fmaf(s, wb.y, acc[5][k]);
                acc[6][k] = fmaf(s, wb.z, acc[6][k]);
                acc[7][k] = fmaf(s, wb.w, acc[7][k]);
            }
        }
#pragma unroll
        for (int k = 0; k < 4; ++k) {
            if (k0 + k < cnt) {
#pragma unroll
                for (int c = 0; c < 8; ++c) mv[c] = fmaxf(mv[c], acc[c][k]);
            }
        }
    }
    __syncthreads();
    float* red = sh1;                 // group-local reuse as [8][COUT]
#pragma unroll
    for (int c = 0; c < 8; ++c) red[kg * COUT + o0 + c] = mv[c];
    __syncthreads();
    float m = red[t];
#pragma unroll
    for (int r = 1; r < 8; ++r) m = fmaxf(m, red[r * COUT + t]);
    float res = (cnt > 0) ? fmaxf(m + b2[t], 0.f) : 0.f;
    xout[((size_t)b * N + i) * COUT + t] = res;
}

// ---------------- head ----------------
__global__ void head_kernel(const float* __restrict__ x3,
                            const float* __restrict__ Wc1, const float* __restrict__ bc1,
                            const float* __restrict__ Wc2, const float* __restrict__ bc2,
                            const float* __restrict__ Wc3, const float* __restrict__ bc3,
                            const float* __restrict__ Wd1, const float* __restrict__ bd1,
                            const float* __restrict__ Wd2, const float* __restrict__ bd2,
                            float* __restrict__ out)
{
    __shared__ float sf[256], sh[256], sh2[256], slog[40], sd[2];
    const int b = blockIdx.x, t = threadIdx.x;

    float m = -FLT_MAX;
    for (int n = 0; n < N3; ++n)
        m = fmaxf(m, x3[((size_t)b * N3 + n) * 256 + t]);
    sf[t] = m;
    __syncthreads();

    float a = bc1[t];
    for (int c = 0; c < 256; ++c) a = fmaf(sf[c], Wc1[c * 256 + t], a);
    sh[t] = fmaxf(a, 0.f);
    __syncthreads();

    a = bc2[t];
    for (int c = 0; c < 256; ++c) a = fmaf(sh[c], Wc2[c * 256 + t], a);
    sh2[t] = fmaxf(a, 0.f);
    __syncthreads();

    if (t < 40) {
        float l = bc3[t];
        for (int c = 0; c < 256; ++c) l = fmaf(sh2[c], Wc3[c * 40 + t], l);
        slog[t] = l;
    }
    float a2 = bd1[t];
    for (int c = 0; c < 256; ++c) a2 = fmaf(sf[c], Wd1[c * 256 + t], a2);
    a2 = fmaxf(a2, 0.f);
    __syncthreads();
    sh[t] = a2;
    __syncthreads();
    if (t < 2) {
        float l = bd2[t];
        for (int c = 0; c < 256; ++c) l = fmaf(sh[c], Wd2[c * 2 + t], l);
        sd[t] = l;
    }
    __syncthreads();

    if (t < 40) {
        float mx = -FLT_MAX;
        for (int j = 0; j < 40; ++j) mx = fmaxf(mx, slog[j]);
        float se = 0.f;
        for (int j = 0; j < 40; ++j) se += expf(slog[j] - mx);
        out[b * 40 + t] = slog[t] - mx - logf(se);
    }
    if (t < 2) {
        float mx = fmaxf(sd[0], sd[1]);
        float se = expf(sd[0] - mx) + expf(sd[1] - mx);
        out[NB * 40 + b * 2 + t] = sd[t] - mx - logf(se);
    }
}

// ---------------- launch ----------------
extern "C" void kernel_launch(void* const* d_in, const int* in_sizes, int n_in,
                              void* d_out, int out_size)
{
    const float* pos = (const float*)d_in[0];
    const float* W1a = (const float*)d_in[1];  const float* b1a = (const float*)d_in[2];
    const float* W1b = (const float*)d_in[3];  const float* b1b = (const float*)d_in[4];
    const float* W2a = (const float*)d_in[5];  const float* b2a = (const float*)d_in[6];
    const float* W2b = (const float*)d_in[7];  const float* b2b = (const float*)d_in[8];
    const float* W3a = (const float*)d_in[9];  const float* b3a = (const float*)d_in[10];
    const float* W3b = (const float*)d_in[11]; const float* b3b = (const float*)d_in[12];
    const float* Wc1 = (const float*)d_in[13]; const float* bc1 = (const float*)d_in[14];
    const float* Wc2 = (const float*)d_in[15]; const float* bc2 = (const float*)d_in[16];
    const float* Wc3 = (const float*)d_in[17]; const float* bc3 = (const float*)d_in[18];
    const float* Wd1 = (const float*)d_in[19]; const float* bd1 = (const float*)d_in[20];
    const float* Wd2 = (const float*)d_in[21]; const float* bd2 = (const float*)d_in[22];
    float* out = (float*)d_out;

    void *p_idx1, *p_cnt1, *p_a1, *p_x1, *p_fi1, *p_pos2, *p_x2g, *p_a2,
         *p_idx2, *p_cnt2, *p_x2, *p_fi2, *p_pos3, *p_x3g, *p_a3,
         *p_idx3, *p_cnt3, *p_x3, *p_pm1, *p_pm2, *p_pm3;
    cudaGetSymbolAddress(&p_idx1, g_idx1);
    cudaGetSymbolAddress(&p_cnt1, g_cnt1);
    cudaGetSymbolAddress(&p_a1,   g_a1);
    cudaGetSymbolAddress(&p_x1,   g_x1);
    cudaGetSymbolAddress(&p_fi1,  g_fi1);
    cudaGetSymbolAddress(&p_pos2, g_pos2);
    cudaGetSymbolAddress(&p_x2g,  g_x2g);
    cudaGetSymbolAddress(&p_a2,   g_a2);
    cudaGetSymbolAddress(&p_idx2, g_idx2);
    cudaGetSymbolAddress(&p_cnt2, g_cnt2);
    cudaGetSymbolAddress(&p_x2,   g_x2);
    cudaGetSymbolAddress(&p_fi2,  g_fi2);
    cudaGetSymbolAddress(&p_pos3, g_pos3);
    cudaGetSymbolAddress(&p_x3g,  g_x3g);
    cudaGetSymbolAddress(&p_a3,   g_a3);
    cudaGetSymbolAddress(&p_idx3, g_idx3);
    cudaGetSymbolAddress(&p_cnt3, g_cnt3);
    cudaGetSymbolAddress(&p_x3,   g_x3);
    cudaGetSymbolAddress(&p_pm1,  g_perm1);
    cudaGetSymbolAddress(&p_pm2,  g_perm2);
    cudaGetSymbolAddress(&p_pm3,  g_perm3);

    const int smMega1 = N1 * 12 + 128;
    const int smMega2 = N2 * 12 + 128;
    const int smKnn3  = 256 * 16;
    const int shc1 = 4 * (32 * (64 + 4)  + 64)  * 4;   // 35840
    const int shc2 = 2 * (32 * (128 + 4) + 128) * 4;   // 34816
    const int shc3 = 1 * (32 * (256 + 4) + 256) * 4;   // 34304
    cudaFuncSetAttribute(mega_kernel<16>,
                         cudaFuncAttributeMaxDynamicSharedMemorySize, 50176);

    const float r1 = 0.2f, r2 = 0.4f, r3 = 1.0f;

    // level 1
    binsort_kernel<5><<<NB, 256>>>(pos, N1, (int*)p_pm1);
    node_pre_kernel<0, 64><<<(NB * N1 * 64) / 256, 256>>>(
        nullptr, pos, W1a, b1a, (float*)p_a1, NB * N1);
    mega_kernel<16><<<NB + (N1 / 256) * NB, 256, smMega1>>>(
        pos, r1 * r1, (int*)p_idx1, (int*)p_cnt1, N2, (int*)p_fi1, (int*)p_pm1);
    conv_kernel<64, 64, 4><<<dim3(N1 / 4, NB), 256, shc1>>>(
        (float*)p_a1, pos, (int*)p_idx1, (int*)p_cnt1,
        W1a, W1b, b1b, (float*)p_x1, N1);
    gather_kernel<<<256, 256>>>((float*)p_x1, pos, (int*)p_fi1,
                                (float*)p_x2g, (float*)p_pos2, N1, N2, 64);

    // level 2
    binsort_kernel<4><<<NB, 256>>>((float*)p_pos2, N2, (int*)p_pm2);
    node_pre_kernel<64, 128><<<(NB * N2 * 128) / 256, 256>>>(
        (float*)p_x2g, (float*)p_pos2, W2a, b2a, (float*)p_a2, NB * N2);
    mega_kernel<8><<<NB + (N2 / 256) * NB, 256, smMega2>>>(
        (float*)p_pos2, r2 * r2, (int*)p_idx2, (int*)p_cnt2, N3, (int*)p_fi2,
        (int*)p_pm2);
    conv_kernel<128, 128, 2><<<dim3(N2 / 2, NB), 256, shc2>>>(
        (float*)p_a2, (float*)p_pos2, (int*)p_idx2, (int*)p_cnt2,
        W2a + 64 * 128, W2b, b2b, (float*)p_x2, N2);
    gather_kernel<<<256, 256>>>((float*)p_x2, (float*)p_pos2, (int*)p_fi2,
                                (float*)p_x3g, (float*)p_pos3, N2, N3, 128);

    // level 3
    binsort_kernel<4><<<NB, 256>>>((float*)p_pos3, N3, (int*)p_pm3);
    node_pre_kernel<128, 256><<<(NB * N3 * 256) / 256, 256>>>(
        (float*)p_x3g, (float*)p_pos3, W3a, b3a, (float*)p_a3, NB * N3);
    knn_kernel<<<(N3 / 256) * NB, 256, smKnn3>>>(
        (float*)p_pos3, N3, r3 * r3, (int*)p_idx3, (int*)p_cnt3, (int*)p_pm3);
    conv_kernel<256, 256, 1><<<dim3(N3, NB), 256, shc3>>>(
        (float*)p_a3, (float*)p_pos3, (int*)p_idx3, (int*)p_cnt3,
        W3a + 128 * 256, W3b, b3b, (float*)p_x3, N3);

    // head
    head_kernel<<<NB, 256>>>((float*)p_x3, Wc1, bc1, Wc2, bc2, Wc3, bc3,
                             Wd1, bd1, Wd2, bd2, out);

    (void)in_sizes; (void)n_in; (void)out_size;
}

// round 9
// speedup vs baseline: 1.4084x; 1.1502x over previous
#include <cuda_runtime.h>
#include <math.h>
#include <float.h>

typedef unsigned int u32;

static constexpr int NB = 8, N1 = 4096, N2 = 2048, N3 = 512, KNN = 32;

// ---------------- scratch ----------------
__device__ int   g_idx1[NB * N1 * KNN];
__device__ int   g_cnt1[NB * N1];
__device__ float g_a1  [NB * N1 * 64];
__device__ float g_x1  [NB * N1 * 64];
__device__ int   g_fi1 [NB * N2];
__device__ float g_pos2[NB * N2 * 3];
__device__ float g_x2g [NB * N2 * 64];
__device__ float g_a2  [NB * N2 * 128];
__device__ int   g_idx2[NB * N2 * KNN];
__device__ int   g_cnt2[NB * N2];
__device__ float g_x2  [NB * N2 * 128];
__device__ int   g_fi2 [NB * N3];
__device__ float g_pos3[NB * N3 * 3];
__device__ float g_x3g [NB * N3 * 128];
__device__ float g_a3  [NB * N3 * 256];
__device__ int   g_idx3[NB * N3 * KNN];
__device__ int   g_cnt3[NB * N3];
__device__ float g_x3  [NB * N3 * 256];
__device__ int   g_perm1[NB * N1];
__device__ int   g_perm2[NB * N2];
__device__ int   g_perm3[NB * N3];

// ---------------- spatial counting sort (query coherence for KNN) --------
template <int NBIN>
__global__ void __launch_bounds__(256)
binsort_kernel(const float* __restrict__ pos, int N, int* __restrict__ perm)
{
    constexpr int B3 = NBIN * NBIN * NBIN;
    __shared__ int hist[B3];
    __shared__ int offs[B3];
    const int b = blockIdx.x, t = threadIdx.x;
    const float* pb = pos + (size_t)b * N * 3;

    for (int e = t; e < B3; e += 256) hist[e] = 0;
    __syncthreads();
    for (int i = t; i < N; i += 256) {
        int ix = min(NBIN - 1, max(0, (int)(pb[i * 3 + 0] * NBIN)));
        int iy = min(NBIN - 1, max(0, (int)(pb[i * 3 + 1] * NBIN)));
        int iz = min(NBIN - 1, max(0, (int)(pb[i * 3 + 2] * NBIN)));
        atomicAdd(&hist[(ix * NBIN + iy) * NBIN + iz], 1);
    }
    __syncthreads();
    if (t == 0) {
        int acc = 0;
        for (int k = 0; k < B3; ++k) { offs[k] = acc; acc += hist[k]; }
    }
    __syncthreads();
    for (int e = t; e < B3; e += 256) hist[e] = 0;
    __syncthreads();
    for (int i = t; i < N; i += 256) {
        int ix = min(NBIN - 1, max(0, (int)(pb[i * 3 + 0] * NBIN)));
        int iy = min(NBIN - 1, max(0, (int)(pb[i * 3 + 1] * NBIN)));
        int iz = min(NBIN - 1, max(0, (int)(pb[i * 3 + 2] * NBIN)));
        int key = (ix * NBIN + iy) * NBIN + iz;
        int r = offs[key] + atomicAdd(&hist[key], 1);
        perm[b * N + r] = i;
    }
}

// ---------------- per-node a_j = [x_j, pos_j] @ W1 + b1 ----------------
template <int CINX, int CHID>
__global__ void __launch_bounds__(256)
node_pre_kernel(const float* __restrict__ x, const float* __restrict__ pos,
                const float* __restrict__ W1, const float* __restrict__ b1,
                float* __restrict__ a, int nNodes)
{
    int tid = blockIdx.x * 256 + threadIdx.x;
    if (tid >= nNodes * CHID) return;
    int node = tid / CHID, c = tid - node * CHID;
    float acc = b1[c];
    if (CINX > 0) {
        const float* xr = x + (size_t)node * CINX;
#pragma unroll 4
        for (int f = 0; f < CINX; ++f)
            acc = fmaf(xr[f], W1[f * CHID + c], acc);
    }
    const float* pr = pos + (size_t)node * 3;
    acc = fmaf(pr[0], W1[(CINX + 0) * CHID + c], acc);
    acc = fmaf(pr[1], W1[(CINX + 1) * CHID + c], acc);
    acc = fmaf(pr[2], W1[(CINX + 2) * CHID + c], acc);
    a[tid] = acc;
}

// ---------------- KNN (256 thr), register top-32, bin-coherent queries ----
__device__ void knn_dev(const float* __restrict__ pb, int N, float r2v,
                        int* __restrict__ oidx, int* __restrict__ ocnt,
                        int qb, const int* __restrict__ perm, float4* sj)
{
    const int t = threadIdx.x;
    const int i = perm[qb * 256 + t];
    const float xi = pb[i * 3 + 0], yi = pb[i * 3 + 1], zi = pb[i * 3 + 2];
    const float sqi = __fadd_rn(__fadd_rn(__fmul_rn(xi, xi), __fmul_rn(yi, yi)),
                                __fmul_rn(zi, zi));
    const float m2x = -2.f * xi, m2y = -2.f * yi, m2z = -2.f * zi;

    float bd[KNN];
    int   bi_[KNN];
#pragma unroll
    for (int k = 0; k < KNN; ++k) { bd[k] = FLT_MAX; bi_[k] = 0; }
    float worst = FLT_MAX;

    for (int t0 = 0; t0 < N; t0 += 256) {
        __syncthreads();
        {
            int j = t0 + t;
            float x = pb[j * 3 + 0], y = pb[j * 3 + 1], z = pb[j * 3 + 2];
            float sq = __fadd_rn(__fadd_rn(__fmul_rn(x, x), __fmul_rn(y, y)),
                                 __fmul_rn(z, z));
            sj[t] = make_float4(x, y, z, sq);
        }
        __syncthreads();
#pragma unroll 2
        for (int jj = 0; jj < 256; ++jj) {
            float4 q = sj[jj];
            float d2 = sqi + fmaf(m2x, q.x, fmaf(m2y, q.y, fmaf(m2z, q.z, q.w)));
            int j = t0 + jj;
            if (d2 <= r2v && d2 < worst && j != i) {
#pragma unroll
                for (int k = KNN - 1; k > 0; --k) {
                    if (bd[k - 1] > d2)  { bd[k] = bd[k - 1]; bi_[k] = bi_[k - 1]; }
                    else if (bd[k] > d2) { bd[k] = d2;        bi_[k] = j; }
                }
                if (bd[0] > d2)          { bd[0] = d2;        bi_[0] = j; }
                worst = bd[KNN - 1];
            }
        }
    }
    int cnt = 0;
#pragma unroll
    for (int k = 0; k < KNN; ++k) cnt += (bd[k] <= r2v) ? 1 : 0;
    ocnt[i] = cnt;
    const int base = i * KNN;
#pragma unroll
    for (int k = 0; k < KNN; ++k) oidx[base + k] = bi_[k];
}

// ---------------- FPS (256 threads): single barrier per iteration --------
template <int P>
__device__ void fps_dev(const float* __restrict__ pb, int nS,
                        int* __restrict__ out, float* sm)
{
    const int N = P * 256;
    float* spos = sm;
    u32*  svb = (u32*)(sm + N * 3);
    int*  si  = (int*)(svb + 16);
    const int t = threadIdx.x, w = t >> 5, l = t & 31;

    for (int e = t; e < N * 3; e += 256) spos[e] = pb[e];
    __syncthreads();

    float px[P], py[P], pz[P], mind[P];
    const float x0 = spos[0], y0 = spos[1], z0 = spos[2];
    float bv = -1.f; int bidx = 0x7fffffff;
#pragma unroll
    for (int p = 0; p < P; ++p) {
        int i = t + p * 256;
        px[p] = spos[i * 3 + 0]; py[p] = spos[i * 3 + 1]; pz[p] = spos[i * 3 + 2];
        float dx = px[p] - x0, dy = py[p] - y0, dz = pz[p] - z0;
        mind[p] = __fadd_rn(__fadd_rn(__fmul_rn(dx, dx), __fmul_rn(dy, dy)),
                            __fmul_rn(dz, dz));
        if (mind[p] > bv) { bv = mind[p]; bidx = i; }
    }
    if (t == 0) out[0] = 0;

    int par = 0;
    for (int s = 1; s < nS; ++s) {
        u32 vb = __float_as_uint(bv);
        u32 m  = __reduce_max_sync(0xffffffffu, vb);
        u32 cand = (vb == m) ? (u32)bidx : 0xffffffffu;
        u32 wi = __reduce_min_sync(0xffffffffu, cand);
        if (l == 0) { svb[par * 8 + w] = m; si[par * 8 + w] = (int)wi; }
        __syncthreads();
        u32 v2 = (l < 8) ? svb[par * 8 + l] : 0u;
        u32 i2 = (l < 8) ? (u32)si[par * 8 + l] : 0xffffffffu;
        u32 m2 = __reduce_max_sync(0xffffffffu, v2);
        u32 c2 = (v2 == m2 && l < 8) ? i2 : 0xffffffffu;
        u32 gi = __reduce_min_sync(0xffffffffu, c2);
        if (t == 0) out[s] = (int)gi;
        const float cx = spos[gi * 3 + 0];
        const float cy = spos[gi * 3 + 1];
        const float cz = spos[gi * 3 + 2];
        par ^= 1;
        bv = -1.f; bidx = 0x7fffffff;
#pragma unroll
        for (int p = 0; p < P; ++p) {
            float dx = px[p] - cx, dy = py[p] - cy, dz = pz[p] - cz;
            float d = __fadd_rn(__fadd_rn(__fmul_rn(dx, dx), __fmul_rn(dy, dy)),
                                __fmul_rn(dz, dz));
            mind[p] = fminf(mind[p], d);
            if (mind[p] > bv) { bv = mind[p]; bidx = t + p * 256; }
        }
    }
}

// ---------------- fused KNN + FPS launch ----------------
template <int P>
__global__ void __launch_bounds__(256, 1)
mega_kernel(const float* __restrict__ pos, float r2v,
            int* __restrict__ oidx, int* __restrict__ ocnt,
            int nS, int* __restrict__ fi, const int* __restrict__ perm)
{
    extern __shared__ char sm[];
    const int N = P * 256;
    if (blockIdx.x < NB) {
        fps_dev<P>(pos + (size_t)blockIdx.x * N * 3, nS,
                   fi + blockIdx.x * nS, (float*)sm);
    } else {
        int kb = blockIdx.x - NB;
        int b = kb % NB, qb = kb / NB;
        knn_dev(pos + (size_t)b * N * 3, N, r2v,
                oidx + (size_t)b * N * KNN, ocnt + b * N, qb,
                perm + b * N, (float4*)sm);
    }
}

__global__ void __launch_bounds__(256, 1)
knn_kernel(const float* __restrict__ pos, int N, float r2v,
           int* __restrict__ oidx, int* __restrict__ ocnt,
           const int* __restrict__ perm)
{
    extern __shared__ char sm[];
    int b = blockIdx.x % NB, qb = blockIdx.x / NB;
    knn_dev(pos + (size_t)b * N * 3, N, r2v,
            oidx + (size_t)b * N * KNN, ocnt + b * N, qb,
            perm + b * N, (float4*)sm);
}

// ---------------- gather after FPS ----------------
__global__ void gather_kernel(const float* __restrict__ xin,
                              const float* __restrict__ posin,
                              const int* __restrict__ fi,
                              float* __restrict__ xo, float* __restrict__ poso,
                              int Nin, int Nout, int C)
{
    const int tid = blockIdx.x * blockDim.x + threadIdx.x;
    const int stride = gridDim.x * blockDim.x;
    const int totX = NB * Nout * C;
    for (int e = tid; e < totX; e += stride) {
        int c = e % C, m = (e / C) % Nout, b = e / (C * Nout);
        int j = fi[b * Nout + m];
        xo[e] = xin[((size_t)b * Nin + j) * C + c];
    }
    const int totP = NB * Nout * 3;
    for (int e = tid; e < totP; e += stride) {
        int d = e % 3, m = (e / 3) % Nout, b = e / (3 * Nout);
        int j = fi[b * Nout + m];
        poso[e] = posin[((size_t)b * Nin + j) * 3 + d];
    }
}

// ---------------- PointNetConv: transposed-h smem + 8x8 register tile ----
// Per point: D = h[32 x CHID] @ W2[CHID x COUT], masked max over rows.
// hT stored [CHID][36] (k-major contiguous) so phase-2 h reads are LDS.128.
// Thread tile: 8 cols x 8 rows. TPP = COUT/2 threads per point.
template <int CHID, int COUT>
__global__ void __launch_bounds__(256, 2)
conv_kernel(const float* __restrict__ a, const float* __restrict__ pos,
            const int* __restrict__ kidx, const int* __restrict__ kcnt,
            const float* __restrict__ W1p, const float* __restrict__ W2,
            const float* __restrict__ b2, float* __restrict__ xout, int N)
{
    constexpr int TPP = COUT / 2;
    constexpr int PPB = 256 / TPP;
    constexpr int HS  = 36;                  // k-stride (16B aligned, bank-ok)
    constexpr int GSZ = CHID * HS + CHID;
    extern __shared__ float smem[];
    const int tg = threadIdx.x / TPP;
    const int tp = threadIdx.x % TPP;
    float* hT  = smem + tg * GSZ;            // [CHID][HS]
    float* scv = hT + CHID * HS;             // [CHID]
    __shared__ int   sidx[PPB][KNN];
    __shared__ float spi[PPB][3];
    __shared__ int   scnt[PPB];

    const int b = blockIdx.y;
    const int i = blockIdx.x * PPB + tg;

    if (tp < KNN) sidx[tg][tp] = kidx[((size_t)b * N + i) * KNN + tp];
    if (tp == 0)  scnt[tg] = kcnt[b * N + i];
    if (tp < 3)   spi[tg][tp] = pos[((size_t)b * N + i) * 3 + tp];
    __syncthreads();
    const int cnt = scnt[tg];
    const float p0 = spi[tg][0], p1 = spi[tg][1], p2 = spi[tg][2];
    for (int c = tp; c < CHID; c += TPP)
        scv[c] = fmaf(p2, W1p[2 * CHID + c],
                      fmaf(p1, W1p[CHID + c], p0 * W1p[c]));
    __syncthreads();

    // gather transposed: thread = (4-neighbor quad kq, channel c)
    const float* ab = a + (size_t)b * N * CHID;
    for (int e = tp; e < 8 * CHID; e += TPP) {
        int kq = e / CHID, c = e - kq * CHID;
        float cv = scv[c];
        int j0 = sidx[tg][kq * 4 + 0], j1 = sidx[tg][kq * 4 + 1];
        int j2 = sidx[tg][kq * 4 + 2], j3 = sidx[tg][kq * 4 + 3];
        float4 h;
        h.x = fmaxf(ab[(size_t)j0 * CHID + c] - cv, 0.f);
        h.y = fmaxf(ab[(size_t)j1 * CHID + c] - cv, 0.f);
        h.z = fmaxf(ab[(size_t)j2 * CHID + c] - cv, 0.f);
        h.w = fmaxf(ab[(size_t)j3 * CHID + c] - cv, 0.f);
        *(float4*)&hT[c * HS + kq * 4] = h;
    }
    __syncthreads();

    // phase 2: 8 cols x 8 rows per thread
    constexpr int CG = COUT / 8;
    const int o0 = (tp % CG) * 8;
    const int kg = tp / CG;
    const int k0 = kg * 8;
    float acc[8][8];
#pragma unroll
    for (int c = 0; c < 8; ++c)
#pragma unroll
        for (int r = 0; r < 8; ++r) acc[c][r] = 0.f;

#pragma unroll 2
    for (int cc = 0; cc < CHID; ++cc) {
        float4 wa = *(const float4*)&W2[cc * COUT + o0];
        float4 wb = *(const float4*)&W2[cc * COUT + o0 + 4];
        float4 ha = *(const float4*)&hT[cc * HS + k0];
        float4 hb = *(const float4*)&hT[cc * HS + k0 + 4];
        float wv[8] = { wa.x, wa.y, wa.z, wa.w, wb.x, wb.y, wb.z, wb.w };
        float hv[8] = { ha.x, ha.y, ha.z, ha.w, hb.x, hb.y, hb.z, hb.w };
#pragma unroll
        for (int c = 0; c < 8; ++c)
#pragma unroll
            for (int r = 0; r < 8; ++r)
                acc[c][r] = fmaf(wv[c], hv[r], acc[c][r]);
    }

    float mv[8];
#pragma unroll
    for (int c = 0; c < 8; ++c) mv[c] = -FLT_MAX;
#pragma unroll
    for (int r = 0; r < 8; ++r) {
        if (k0 + r < cnt) {
#pragma unroll
            for (int c = 0; c < 8; ++c) mv[c] = fmaxf(mv[c], acc[c][r]);
        }
    }
    __syncthreads();                          // hT reads done; reuse as red
    float* red = hT;                          // [4][COUT]
#pragma unroll
    for (int c = 0; c < 8; ++c) red[kg * COUT + o0 + c] = mv[c];
    __syncthreads();
#pragma unroll
    for (int q = 0; q < 2; ++q) {
        int c = tp * 2 + q;
        float m = fmaxf(fmaxf(red[c], red[COUT + c]),
                        fmaxf(red[2 * COUT + c], red[3 * COUT + c]));
        float res = (cnt > 0) ? fmaxf(m + b2[c], 0.f) : 0.f;
        xout[((size_t)b * N + i) * COUT + c] = res;
    }
}

// ---------------- head ----------------
__global__ void head_kernel(const float* __restrict__ x3,
                            const float* __restrict__ Wc1, const float* __restrict__ bc1,
                            const float* __restrict__ Wc2, const float* __restrict__ bc2,
                            const float* __restrict__ Wc3, const float* __restrict__ bc3,
                            const float* __restrict__ Wd1, const float* __restrict__ bd1,
                            const float* __restrict__ Wd2, const float* __restrict__ bd2,
                            float* __restrict__ out)
{
    __shared__ float sf[256], sh[256], sh2[256], slog[40], sd[2];
    const int b = blockIdx.x, t = threadIdx.x;

    float m = -FLT_MAX;
    for (int n = 0; n < N3; ++n)
        m = fmaxf(m, x3[((size_t)b * N3 + n) * 256 + t]);
    sf[t] = m;
    __syncthreads();

    float a = bc1[t];
    for (int c = 0; c < 256; ++c) a = fmaf(sf[c], Wc1[c * 256 + t], a);
    sh[t] = fmaxf(a, 0.f);
    __syncthreads();

    a = bc2[t];
    for (int c = 0; c < 256; ++c) a = fmaf(sh[c], Wc2[c * 256 + t], a);
    sh2[t] = fmaxf(a, 0.f);
    __syncthreads();

    if (t < 40) {
        float l = bc3[t];
        for (int c = 0; c < 256; ++c) l = fmaf(sh2[c], Wc3[c * 40 + t], l);
        slog[t] = l;
    }
    float a2 = bd1[t];
    for (int c = 0; c < 256; ++c) a2 = fmaf(sf[c], Wd1[c * 256 + t], a2);
    a2 = fmaxf(a2, 0.f);
    __syncthreads();
    sh[t] = a2;
    __syncthreads();
    if (t < 2) {
        float l = bd2[t];
        for (int c = 0; c < 256; ++c) l = fmaf(sh[c], Wd2[c * 2 + t], l);
        sd[t] = l;
    }
    __syncthreads();

    if (t < 40) {
        float mx = -FLT_MAX;
        for (int j = 0; j < 40; ++j) mx = fmaxf(mx, slog[j]);
        float se = 0.f;
        for (int j = 0; j < 40; ++j) se += expf(slog[j] - mx);
        out[b * 40 + t] = slog[t] - mx - logf(se);
    }
    if (t < 2) {
        float mx = fmaxf(sd[0], sd[1]);
        float se = expf(sd[0] - mx) + expf(sd[1] - mx);
        out[NB * 40 + b * 2 + t] = sd[t] - mx - logf(se);
    }
}

// ---------------- launch ----------------
extern "C" void kernel_launch(void* const* d_in, const int* in_sizes, int n_in,
                              void* d_out, int out_size)
{
    const float* pos = (const float*)d_in[0];
    const float* W1a = (const float*)d_in[1];  const float* b1a = (const float*)d_in[2];
    const float* W1b = (const float*)d_in[3];  const float* b1b = (const float*)d_in[4];
    const float* W2a = (const float*)d_in[5];  const float* b2a = (const float*)d_in[6];
    const float* W2b = (const float*)d_in[7];  const float* b2b = (const float*)d_in[8];
    const float* W3a = (const float*)d_in[9];  const float* b3a = (const float*)d_in[10];
    const float* W3b = (const float*)d_in[11]; const float* b3b = (const float*)d_in[12];
    const float* Wc1 = (const float*)d_in[13]; const float* bc1 = (const float*)d_in[14];
    const float* Wc2 = (const float*)d_in[15]; const float* bc2 = (const float*)d_in[16];
    const float* Wc3 = (const float*)d_in[17]; const float* bc3 = (const float*)d_in[18];
    const float* Wd1 = (const float*)d_in[19]; const float* bd1 = (const float*)d_in[20];
    const float* Wd2 = (const float*)d_in[21]; const float* bd2 = (const float*)d_in[22];
    float* out = (float*)d_out;

    void *p_idx1, *p_cnt1, *p_a1, *p_x1, *p_fi1, *p_pos2, *p_x2g, *p_a2,
         *p_idx2, *p_cnt2, *p_x2, *p_fi2, *p_pos3, *p_x3g, *p_a3,
         *p_idx3, *p_cnt3, *p_x3, *p_pm1, *p_pm2, *p_pm3;
    cudaGetSymbolAddress(&p_idx1, g_idx1);
    cudaGetSymbolAddress(&p_cnt1, g_cnt1);
    cudaGetSymbolAddress(&p_a1,   g_a1);
    cudaGetSymbolAddress(&p_x1,   g_x1);
    cudaGetSymbolAddress(&p_fi1,  g_fi1);
    cudaGetSymbolAddress(&p_pos2, g_pos2);
    cudaGetSymbolAddress(&p_x2g,  g_x2g);
    cudaGetSymbolAddress(&p_a2,   g_a2);
    cudaGetSymbolAddress(&p_idx2, g_idx2);
    cudaGetSymbolAddress(&p_cnt2, g_cnt2);
    cudaGetSymbolAddress(&p_x2,   g_x2);
    cudaGetSymbolAddress(&p_fi2,  g_fi2);
    cudaGetSymbolAddress(&p_pos3, g_pos3);
    cudaGetSymbolAddress(&p_x3g,  g_x3g);
    cudaGetSymbolAddress(&p_a3,   g_a3);
    cudaGetSymbolAddress(&p_idx3, g_idx3);
    cudaGetSymbolAddress(&p_cnt3, g_cnt3);
    cudaGetSymbolAddress(&p_x3,   g_x3);
    cudaGetSymbolAddress(&p_pm1,  g_perm1);
    cudaGetSymbolAddress(&p_pm2,  g_perm2);
    cudaGetSymbolAddress(&p_pm3,  g_perm3);

    const int smMega1 = N1 * 12 + 128;
    const int smMega2 = N2 * 12 + 128;
    const int smKnn3  = 256 * 16;
    const int shc1 = 8 * (64 * 37)  * 4;   // 75776
    const int shc2 = 4 * (128 * 37) * 4;   // 75776
    const int shc3 = 2 * (256 * 37) * 4;   // 75776
    cudaFuncSetAttribute(mega_kernel<16>,
                         cudaFuncAttributeMaxDynamicSharedMemorySize, 50176);
    cudaFuncSetAttribute(conv_kernel<64, 64>,
                         cudaFuncAttributeMaxDynamicSharedMemorySize, 76800);
    cudaFuncSetAttribute(conv_kernel<128, 128>,
                         cudaFuncAttributeMaxDynamicSharedMemorySize, 76800);
    cudaFuncSetAttribute(conv_kernel<256, 256>,
                         cudaFuncAttributeMaxDynamicSharedMemorySize, 76800);

    const float r1 = 0.2f, r2 = 0.4f, r3 = 1.0f;

    // level 1
    binsort_kernel<5><<<NB, 256>>>(pos, N1, (int*)p_pm1);
    node_pre_kernel<0, 64><<<(NB * N1 * 64) / 256, 256>>>(
        nullptr, pos, W1a, b1a, (float*)p_a1, NB * N1);
    mega_kernel<16><<<NB + (N1 / 256) * NB, 256, smMega1>>>(
        pos, r1 * r1, (int*)p_idx1, (int*)p_cnt1, N2, (int*)p_fi1, (int*)p_pm1);
    conv_kernel<64, 64><<<dim3(N1 / 8, NB), 256, shc1>>>(
        (float*)p_a1, pos, (int*)p_idx1, (int*)p_cnt1,
        W1a, W1b, b1b, (float*)p_x1, N1);
    gather_kernel<<<256, 256>>>((float*)p_x1, pos, (int*)p_fi1,
                                (float*)p_x2g, (float*)p_pos2, N1, N2, 64);

    // level 2
    binsort_kernel<4><<<NB, 256>>>((float*)p_pos2, N2, (int*)p_pm2);
    node_pre_kernel<64, 128><<<(NB * N2 * 128) / 256, 256>>>(
        (float*)p_x2g, (float*)p_pos2, W2a, b2a, (float*)p_a2, NB * N2);
    mega_kernel<8><<<NB + (N2 / 256) * NB, 256, smMega2>>>(
        (float*)p_pos2, r2 * r2, (int*)p_idx2, (int*)p_cnt2, N3, (int*)p_fi2,
        (int*)p_pm2);
    conv_kernel<128, 128><<<dim3(N2 / 4, NB), 256, shc2>>>(
        (float*)p_a2, (float*)p_pos2, (int*)p_idx2, (int*)p_cnt2,
        W2a + 64 * 128, W2b, b2b, (float*)p_x2, N2);
    gather_kernel<<<256, 256>>>((float*)p_x2, (float*)p_pos2, (int*)p_fi2,
                                (float*)p_x3g, (float*)p_pos3, N2, N3, 128);

    // level 3
    binsort_kernel<4><<<NB, 256>>>((float*)p_pos3, N3, (int*)p_pm3);
    node_pre_kernel<128, 256><<<(NB * N3 * 256) / 256, 256>>>(
        (float*)p_x3g, (float*)p_pos3, W3a, b3a, (float*)p_a3, NB * N3);
    knn_kernel<<<(N3 / 256) * NB, 256, smKnn3>>>(
        (float*)p_pos3, N3, r3 * r3, (int*)p_idx3, (int*)p_cnt3, (int*)p_pm3);
    conv_kernel<256, 256><<<dim3(N3 / 2, NB), 256, shc3>>>(
        (float*)p_a3, (float*)p_pos3, (int*)p_idx3, (int*)p_cnt3,
        W3a + 128 * 256, W3b, b3b, (float*)p_x3, N3);

    // head
    head_kernel<<<NB, 256>>>((float*)p_x3, Wc1, bc1, Wc2, bc2, Wc3, bc3,
                             Wd1, bd1, Wd2, bd2, out);

    (void)in_sizes; (void)n_in; (void)out_size;
}

// round 10
// speedup vs baseline: 1.7041x; 1.2100x over previous
#include <cuda_runtime.h>
#include <math.h>
#include <float.h>

typedef unsigned int u32;

static constexpr int NB = 8, N1 = 4096, N2 = 2048, N3 = 512, KNN = 32;

// ---------------- scratch ----------------
__device__ int   g_idx1[NB * N1 * KNN];
__device__ int   g_cnt1[NB * N1];
__device__ float g_a1  [NB * N1 * 64];
__device__ float g_x1  [NB * N1 * 64];
__device__ int   g_fi1 [NB * N2];
__device__ float g_pos2[NB * N2 * 3];
__device__ float g_x2g [NB * N2 * 64];
__device__ float g_a2  [NB * N2 * 128];
__device__ int   g_idx2[NB * N2 * KNN];
__device__ int   g_cnt2[NB * N2];
__device__ float g_x2  [NB * N2 * 128];
__device__ int   g_fi2 [NB * N3];
__device__ float g_pos3[NB * N3 * 3];
__device__ float g_x3g [NB * N3 * 128];
__device__ float g_a3  [NB * N3 * 256];
__device__ int   g_idx3[NB * N3 * KNN];
__device__ int   g_cnt3[NB * N3];
__device__ float g_x3  [NB * N3 * 256];
__device__ int   g_perm1[NB * N1];
__device__ int   g_perm2[NB * N2];
__device__ int   g_perm3[NB * N3];
__device__ u32   g_w2t1[4096];     // W2 tf32 fragments, level 1 (64x64)
__device__ u32   g_w2t2[16384];    // level 2 (128x128)
__device__ u32   g_w2t3[65536];    // level 3 (256x256)

// ---------------- tf32 helpers ----------------
__device__ __forceinline__ u32 f2tf32(float f) {
    u32 r; asm("cvt.rna.tf32.f32 %0,%1;" : "=r"(r) : "f"(f)); return r;
}
__device__ __forceinline__ void mma_tf32(float* d, const u32* A, u32 b0, u32 b1) {
    asm("mma.sync.aligned.m16n8k8.row.col.f32.tf32.tf32.f32 "
        "{%0,%1,%2,%3},{%4,%5,%6,%7},{%8,%9},{%0,%1,%2,%3};"
        : "+f"(d[0]), "+f"(d[1]), "+f"(d[2]), "+f"(d[3])
        : "r"(A[0]), "r"(A[1]), "r"(A[2]), "r"(A[3]), "r"(b0), "r"(b1));
}

// ---------------- W2 -> tf32 fragment-major precompute ----------------
// Layout: u32 idx = ((kt*NW + w)*32 + lane)*8 + n*2 + r
//   holds cvt(W2[(kt*8 + lane%4 + r*4)*COUT + (w*32 + n*8 + lane/4)])
template <int CHID, int COUT>
__global__ void __launch_bounds__(256)
w2t_pre_kernel(const float* __restrict__ W2, u32* __restrict__ W2T)
{
    constexpr int NW = COUT / 32;
    int tid = blockIdx.x * 256 + threadIdx.x;
    int lane8 = tid & 255;
    int lane = lane8 >> 3, n = (lane8 & 7) >> 1, r = lane8 & 1;
    int rest = tid >> 8;
    int w = rest % NW, kt = rest / NW;
    int k = kt * 8 + (lane & 3) + r * 4;
    int c = w * 32 + n * 8 + (lane >> 2);
    W2T[tid] = f2tf32(W2[k * COUT + c]);
}

// ---------------- spatial counting sort (query coherence for KNN) --------
template <int NBIN>
__global__ void __launch_bounds__(256)
binsort_kernel(const float* __restrict__ pos, int N, int* __restrict__ perm)
{
    constexpr int B3 = NBIN * NBIN * NBIN;
    __shared__ int hist[B3];
    __shared__ int offs[B3];
    const int b = blockIdx.x, t = threadIdx.x;
    const float* pb = pos + (size_t)b * N * 3;

    for (int e = t; e < B3; e += 256) hist[e] = 0;
    __syncthreads();
    for (int i = t; i < N; i += 256) {
        int ix = min(NBIN - 1, max(0, (int)(pb[i * 3 + 0] * NBIN)));
        int iy = min(NBIN - 1, max(0, (int)(pb[i * 3 + 1] * NBIN)));
        int iz = min(NBIN - 1, max(0, (int)(pb[i * 3 + 2] * NBIN)));
        atomicAdd(&hist[(ix * NBIN + iy) * NBIN + iz], 1);
    }
    __syncthreads();
    if (t == 0) {
        int acc = 0;
        for (int k = 0; k < B3; ++k) { offs[k] = acc; acc += hist[k]; }
    }
    __syncthreads();
    for (int e = t; e < B3; e += 256) hist[e] = 0;
    __syncthreads();
    for (int i = t; i < N; i += 256) {
        int ix = min(NBIN - 1, max(0, (int)(pb[i * 3 + 0] * NBIN)));
        int iy = min(NBIN - 1, max(0, (int)(pb[i * 3 + 1] * NBIN)));
        int iz = min(NBIN - 1, max(0, (int)(pb[i * 3 + 2] * NBIN)));
        int key = (ix * NBIN + iy) * NBIN + iz;
        int r = offs[key] + atomicAdd(&hist[key], 1);
        perm[b * N + r] = i;
    }
}

// ---------------- per-node a_j = [x_j, pos_j] @ W1 + b1 ----------------
template <int CINX, int CHID>
__global__ void __launch_bounds__(256)
node_pre_kernel(const float* __restrict__ x, const float* __restrict__ pos,
                const float* __restrict__ W1, const float* __restrict__ b1,
                float* __restrict__ a, int nNodes)
{
    int tid = blockIdx.x * 256 + threadIdx.x;
    if (tid >= nNodes * CHID) return;
    int node = tid / CHID, c = tid - node * CHID;
    float acc = b1[c];
    if (CINX > 0) {
        const float* xr = x + (size_t)node * CINX;
#pragma unroll 4
        for (int f = 0; f < CINX; ++f)
            acc = fmaf(xr[f], W1[f * CHID + c], acc);
    }
    const float* pr = pos + (size_t)node * 3;
    acc = fmaf(pr[0], W1[(CINX + 0) * CHID + c], acc);
    acc = fmaf(pr[1], W1[(CINX + 1) * CHID + c], acc);
    acc = fmaf(pr[2], W1[(CINX + 2) * CHID + c], acc);
    a[tid] = acc;
}

// ---------------- KNN (512 thr), register top-32, bin-coherent queries ----
__device__ void knn_dev(const float* __restrict__ pb, int N, float r2v,
                        int* __restrict__ oidx, int* __restrict__ ocnt,
                        int qb, const int* __restrict__ perm, float4* sj)
{
    const int t = threadIdx.x;
    const int i = perm[qb * 512 + t];
    const float xi = pb[i * 3 + 0], yi = pb[i * 3 + 1], zi = pb[i * 3 + 2];
    const float sqi = __fadd_rn(__fadd_rn(__fmul_rn(xi, xi), __fmul_rn(yi, yi)),
                                __fmul_rn(zi, zi));
    const float m2x = -2.f * xi, m2y = -2.f * yi, m2z = -2.f * zi;

    float bd[KNN];
    int   bi_[KNN];
#pragma unroll
    for (int k = 0; k < KNN; ++k) { bd[k] = FLT_MAX; bi_[k] = 0; }
    float worst = FLT_MAX;

    for (int t0 = 0; t0 < N; t0 += 512) {
        __syncthreads();
        {
            int j = t0 + t;
            float x = pb[j * 3 + 0], y = pb[j * 3 + 1], z = pb[j * 3 + 2];
            float sq = __fadd_rn(__fadd_rn(__fmul_rn(x, x), __fmul_rn(y, y)),
                                 __fmul_rn(z, z));
            sj[t] = make_float4(x, y, z, sq);
        }
        __syncthreads();
#pragma unroll 2
        for (int jj = 0; jj < 512; ++jj) {
            float4 q = sj[jj];
            float d2 = sqi + fmaf(m2x, q.x, fmaf(m2y, q.y, fmaf(m2z, q.z, q.w)));
            int j = t0 + jj;
            if (d2 <= r2v && d2 < worst && j != i) {
#pragma unroll
                for (int k = KNN - 1; k > 0; --k) {
                    if (bd[k - 1] > d2)  { bd[k] = bd[k - 1]; bi_[k] = bi_[k - 1]; }
                    else if (bd[k] > d2) { bd[k] = d2;        bi_[k] = j; }
                }
                if (bd[0] > d2)          { bd[0] = d2;        bi_[0] = j; }
                worst = bd[KNN - 1];
            }
        }
    }
    int cnt = 0;
#pragma unroll
    for (int k = 0; k < KNN; ++k) cnt += (bd[k] <= r2v) ? 1 : 0;
    ocnt[i] = cnt;
    const int base = i * KNN;
#pragma unroll
    for (int k = 0; k < KNN; ++k) oidx[base + k] = bi_[k];
}

// ---------------- FPS (512 threads): single barrier per iteration --------
template <int P>
__device__ void fps_dev(const float* __restrict__ pb, int nS,
                        int* __restrict__ out, float* sm)
{
    const int N = P * 512;
    float* spos = sm;
    u32*  svb = (u32*)(sm + N * 3);   // [2][16]
    int*  si  = (int*)(svb + 32);     // [2][16]
    const int t = threadIdx.x, w = t >> 5, l = t & 31;

    for (int e = t; e < N * 3; e += 512) spos[e] = pb[e];
    __syncthreads();

    float px[P], py[P], pz[P], mind[P];
    const float x0 = spos[0], y0 = spos[1], z0 = spos[2];
    float bv = -1.f; int bidx = 0x7fffffff;
#pragma unroll
    for (int p = 0; p < P; ++p) {
        int i = t + p * 512;
        px[p] = spos[i * 3 + 0]; py[p] = spos[i * 3 + 1]; pz[p] = spos[i * 3 + 2];
        float dx = px[p] - x0, dy = py[p] - y0, dz = pz[p] - z0;
        mind[p] = __fadd_rn(__fadd_rn(__fmul_rn(dx, dx), __fmul_rn(dy, dy)),
                            __fmul_rn(dz, dz));
        if (mind[p] > bv) { bv = mind[p]; bidx = i; }
    }
    if (t == 0) out[0] = 0;

    int par = 0;
    for (int s = 1; s < nS; ++s) {
        u32 vb = __float_as_uint(bv);
        u32 m  = __reduce_max_sync(0xffffffffu, vb);
        u32 cand = (vb == m) ? (u32)bidx : 0xffffffffu;
        u32 wi = __reduce_min_sync(0xffffffffu, cand);
        if (l == 0) { svb[par * 16 + w] = m; si[par * 16 + w] = (int)wi; }
        __syncthreads();
        u32 v2 = (l < 16) ? svb[par * 16 + l] : 0u;
        u32 i2 = (l < 16) ? (u32)si[par * 16 + l] : 0xffffffffu;
        u32 m2 = __reduce_max_sync(0xffffffffu, v2);
        u32 c2 = (v2 == m2 && l < 16) ? i2 : 0xffffffffu;
        u32 gi = __reduce_min_sync(0xffffffffu, c2);
        if (t == 0) out[s] = (int)gi;
        const float cx = spos[gi * 3 + 0];
        const float cy = spos[gi * 3 + 1];
        const float cz = spos[gi * 3 + 2];
        par ^= 1;
        bv = -1.f; bidx = 0x7fffffff;
#pragma unroll
        for (int p = 0; p < P; ++p) {
            float dx = px[p] - cx, dy = py[p] - cy, dz = pz[p] - cz;
            float d = __fadd_rn(__fadd_rn(__fmul_rn(dx, dx), __fmul_rn(dy, dy)),
                                __fmul_rn(dz, dz));
            mind[p] = fminf(mind[p], d);
            if (mind[p] > bv) { bv = mind[p]; bidx = t + p * 512; }
        }
    }
}

// ---------------- fused KNN + FPS launch ----------------
template <int P>
__global__ void __launch_bounds__(512, 1)
mega_kernel(const float* __restrict__ pos, float r2v,
            int* __restrict__ oidx, int* __restrict__ ocnt,
            int nS, int* __restrict__ fi, const int* __restrict__ perm)
{
    extern __shared__ char sm[];
    const int N = P * 512;
    if (blockIdx.x < NB) {
        fps_dev<P>(pos + (size_t)blockIdx.x * N * 3, nS,
                   fi + blockIdx.x * nS, (float*)sm);
    } else {
        int kb = blockIdx.x - NB;
        int b = kb % NB, qb = kb / NB;
        knn_dev(pos + (size_t)b * N * 3, N, r2v,
                oidx + (size_t)b * N * KNN, ocnt + b * N, qb,
                perm + b * N, (float4*)sm);
    }
}

__global__ void __launch_bounds__(512, 1)
knn_kernel(const float* __restrict__ pos, int N, float r2v,
           int* __restrict__ oidx, int* __restrict__ ocnt,
           const int* __restrict__ perm)
{
    extern __shared__ char sm[];
    int b = blockIdx.x % NB, qb = blockIdx.x / NB;
    knn_dev(pos + (size_t)b * N * 3, N, r2v,
            oidx + (size_t)b * N * KNN, ocnt + b * N, qb,
            perm + b * N, (float4*)sm);
}

// ---------------- gather after FPS ----------------
__global__ void gather_kernel(const float* __restrict__ xin,
                              const float* __restrict__ posin,
                              const int* __restrict__ fi,
                              float* __restrict__ xo, float* __restrict__ poso,
                              int Nin, int Nout, int C)
{
    const int tid = blockIdx.x * blockDim.x + threadIdx.x;
    const int stride = gridDim.x * blockDim.x;
    const int totX = NB * Nout * C;
    for (int e = tid; e < totX; e += stride) {
        int c = e % C, m = (e / C) % Nout, b = e / (C * Nout);
        int j = fi[b * Nout + m];
        xo[e] = xin[((size_t)b * Nin + j) * C + c];
    }
    const int totP = NB * Nout * 3;
    for (int e = tid; e < totP; e += stride) {
        int d = e % 3, m = (e / 3) % Nout, b = e / (3 * Nout);
        int j = fi[b * Nout + m];
        poso[e] = posin[((size_t)b * Nin + j) * 3 + d];
    }
}

// ---------------- PointNetConv on tensor cores (tf32, preconverted W) ----
// CHID == COUT at every level. Group = COUT threads (NW warps) per point.
// hT in smem as tf32 bits, [CHID][HS=40] (A-LDS conflict-free).
// Warp w covers output cols [w*32, w*32+32); B from fragment-major W2T.
template <int CHID, int COUT>
__global__ void __launch_bounds__(256)
conv_mma_kernel(const float* __restrict__ a, const float* __restrict__ pos,
                const int* __restrict__ kidx, const int* __restrict__ kcnt,
                const float* __restrict__ W1p, const u32* __restrict__ W2T,
                const float* __restrict__ b2, float* __restrict__ xout, int N)
{
    constexpr int NW  = COUT / 32;
    constexpr int TPG = COUT;                // threads per point
    constexpr int PPB = 256 / TPG;
    constexpr int KT  = CHID / 8;
    constexpr int HS  = 40;
    constexpr int GSZ = CHID * HS + CHID;
    extern __shared__ float smem[];
    const int tg = threadIdx.x / TPG;
    const int tp = threadIdx.x % TPG;
    u32*   hTu = (u32*)(smem + tg * GSZ);    // [CHID][HS] tf32 bits
    float* scv = smem + tg * GSZ + CHID * HS;
    __shared__ int   sidx[PPB][KNN];
    __shared__ float spi[PPB][3];
    __shared__ int   scnt[PPB];

    const int b = blockIdx.y;
    const int i = blockIdx.x * PPB + tg;

    if (tp < KNN) sidx[tg][tp] = kidx[((size_t)b * N + i) * KNN + tp];
    if (tp == 0)  scnt[tg] = kcnt[b * N + i];
    if (tp < 3)   spi[tg][tp] = pos[((size_t)b * N + i) * 3 + tp];
    __syncthreads();
    const int cnt = scnt[tg];
    const float p0 = spi[tg][0], p1 = spi[tg][1], p2 = spi[tg][2];
    // c == tp (TPG == CHID)
    scv[tp] = fmaf(p2, W1p[2 * CHID + tp],
                   fmaf(p1, W1p[CHID + tp], p0 * W1p[tp]));
    __syncthreads();

    // gather: thread owns channel tp; h = relu(a_j - c_i), store tf32 bits
    const float* ab = a + (size_t)b * N * CHID;
    const float cv = scv[tp];
#pragma unroll
    for (int kq = 0; kq < 8; ++kq) {
        int j0 = sidx[tg][kq * 4 + 0], j1 = sidx[tg][kq * 4 + 1];
        int j2 = sidx[tg][kq * 4 + 2], j3 = sidx[tg][kq * 4 + 3];
        uint4 h;
        h.x = f2tf32(fmaxf(ab[(size_t)j0 * CHID + tp] - cv, 0.f));
        h.y = f2tf32(fmaxf(ab[(size_t)j1 * CHID + tp] - cv, 0.f));
        h.z = f2tf32(fmaxf(ab[(size_t)j2 * CHID + tp] - cv, 0.f));
        h.w = f2tf32(fmaxf(ab[(size_t)j3 * CHID + tp] - cv, 0.f));
        *(uint4*)&hTu[tp * HS + kq * 4] = h;
    }
    __syncthreads();

    // MMA mainloop
    const int lane = tp & 31;
    const int w = tp >> 5;
    const int q = lane >> 2, kk = lane & 3;
    const uint4* Wt = (const uint4*)W2T;

    float d[2][4][4];
#pragma unroll
    for (int m = 0; m < 2; ++m)
#pragma unroll
        for (int n = 0; n < 4; ++n)
#pragma unroll
            for (int r = 0; r < 4; ++r) d[m][n][r] = 0.f;

    for (int kt = 0; kt < KT; ++kt) {
        const u32* col0 = hTu + (kt * 8 + kk) * HS;
        const u32* col4 = col0 + 4 * HS;
        u32 A0[4], A1[4];
        A0[0] = col0[q];       A0[1] = col0[q + 8];
        A0[2] = col4[q];       A0[3] = col4[q + 8];
        A1[0] = col0[16 + q];  A1[1] = col0[16 + q + 8];
        A1[2] = col4[16 + q];  A1[3] = col4[16 + q + 8];
        uint4 B0 = Wt[((kt * NW + w) * 32 + lane) * 2 + 0];
        uint4 B1 = Wt[((kt * NW + w) * 32 + lane) * 2 + 1];
        mma_tf32(d[0][0], A0, B0.x, B0.y);
        mma_tf32(d[0][1], A0, B0.z, B0.w);
        mma_tf32(d[0][2], A0, B1.x, B1.y);
        mma_tf32(d[0][3], A0, B1.z, B1.w);
        mma_tf32(d[1][0], A1, B0.x, B0.y);
        mma_tf32(d[1][1], A1, B0.z, B0.w);
        mma_tf32(d[1][2], A1, B1.x, B1.y);
        mma_tf32(d[1][3], A1, B1.z, B1.w);
    }

    // epilogue: masked row-max, cross-lane reduce, bias + relu
#pragma unroll
    for (int n = 0; n < 4; ++n) {
        float v0 = -FLT_MAX, v1 = -FLT_MAX;
#pragma unroll
        for (int m = 0; m < 2; ++m) {
            int r0 = m * 16 + q, r1 = r0 + 8;
            if (r0 < cnt) { v0 = fmaxf(v0, d[m][n][0]); v1 = fmaxf(v1, d[m][n][1]); }
            if (r1 < cnt) { v0 = fmaxf(v0, d[m][n][2]); v1 = fmaxf(v1, d[m][n][3]); }
        }
        v0 = fmaxf(v0, __shfl_xor_sync(0xffffffffu, v0, 4));
        v1 = fmaxf(v1, __shfl_xor_sync(0xffffffffu, v1, 4));
        v0 = fmaxf(v0, __shfl_xor_sync(0xffffffffu, v0, 8));
        v1 = fmaxf(v1, __shfl_xor_sync(0xffffffffu, v1, 8));
        v0 = fmaxf(v0, __shfl_xor_sync(0xffffffffu, v0, 16));
        v1 = fmaxf(v1, __shfl_xor_sync(0xffffffffu, v1, 16));
        if (lane < 4) {
            int c = w * 32 + n * 8 + lane * 2;
            float o0 = (cnt > 0) ? fmaxf(v0 + b2[c], 0.f) : 0.f;
            float o1 = (cnt > 0) ? fmaxf(v1 + b2[c + 1], 0.f) : 0.f;
            xout[((size_t)b * N + i) * COUT + c]     = o0;
            xout[((size_t)b * N + i) * COUT + c + 1] = o1;
        }
    }
}

// ---------------- head ----------------
__global__ void head_kernel(const float* __restrict__ x3,
                            const float* __restrict__ Wc1, const float* __restrict__ bc1,
                            const float* __restrict__ Wc2, const float* __restrict__ bc2,
                            const float* __restrict__ Wc3, const float* __restrict__ bc3,
                            const float* __restrict__ Wd1, const float* __restrict__ bd1,
                            const float* __restrict__ Wd2, const float* __restrict__ bd2,
                            float* __restrict__ out)
{
    __shared__ float sf[256], sh[256], sh2[256], slog[40], sd[2];
    const int b = blockIdx.x, t = threadIdx.x;

    float m = -FLT_MAX;
    for (int n = 0; n < N3; ++n)
        m = fmaxf(m, x3[((size_t)b * N3 + n) * 256 + t]);
    sf[t] = m;
    __syncthreads();

    float a = bc1[t];
    for (int c = 0; c < 256; ++c) a = fmaf(sf[c], Wc1[c * 256 + t], a);
    sh[t] = fmaxf(a, 0.f);
    __syncthreads();

    a = bc2[t];
    for (int c = 0; c < 256; ++c) a = fmaf(sh[c], Wc2[c * 256 + t], a);
    sh2[t] = fmaxf(a, 0.f);
    __syncthreads();

    if (t < 40) {
        float l = bc3[t];
        for (int c = 0; c < 256; ++c) l = fmaf(sh2[c], Wc3[c * 40 + t], l);
        slog[t] = l;
    }
    float a2 = bd1[t];
    for (int c = 0; c < 256; ++c) a2 = fmaf(sf[c], Wd1[c * 256 + t], a2);
    a2 = fmaxf(a2, 0.f);
    __syncthreads();
    sh[t] = a2;
    __syncthreads();
    if (t < 2) {
        float l = bd2[t];
        for (int c = 0; c < 256; ++c) l = fmaf(sh[c], Wd2[c * 2 + t], l);
        sd[t] = l;
    }
    __syncthreads();

    if (t < 40) {
        float mx = -FLT_MAX;
        for (int j = 0; j < 40; ++j) mx = fmaxf(mx, slog[j]);
        float se = 0.f;
        for (int j = 0; j < 40; ++j) se += expf(slog[j] - mx);
        out[b * 40 + t] = slog[t] - mx - logf(se);
    }
    if (t < 2) {
        float mx = fmaxf(sd[0], sd[1]);
        float se = expf(sd[0] - mx) + expf(sd[1] - mx);
        out[NB * 40 + b * 2 + t] = sd[t] - mx - logf(se);
    }
}

// ---------------- launch ----------------
extern "C" void kernel_launch(void* const* d_in, const int* in_sizes, int n_in,
                              void* d_out, int out_size)
{
    const float* pos = (const float*)d_in[0];
    const float* W1a = (const float*)d_in[1];  const float* b1a = (const float*)d_in[2];
    const float* W1b = (const float*)d_in[3];  const float* b1b = (const float*)d_in[4];
    const float* W2a = (const float*)d_in[5];  const float* b2a = (const float*)d_in[6];
    const float* W2b = (const float*)d_in[7];  const float* b2b = (const float*)d_in[8];
    const float* W3a = (const float*)d_in[9];  const float* b3a = (const float*)d_in[10];
    const float* W3b = (const float*)d_in[11]; const float* b3b = (const float*)d_in[12];
    const float* Wc1 = (const float*)d_in[13]; const float* bc1 = (const float*)d_in[14];
    const float* Wc2 = (const float*)d_in[15]; const float* bc2 = (const float*)d_in[16];
    const float* Wc3 = (const float*)d_in[17]; const float* bc3 = (const float*)d_in[18];
    const float* Wd1 = (const float*)d_in[19]; const float* bd1 = (const float*)d_in[20];
    const float* Wd2 = (const float*)d_in[21]; const float* bd2 = (const float*)d_in[22];
    float* out = (float*)d_out;

    void *p_idx1, *p_cnt1, *p_a1, *p_x1, *p_fi1, *p_pos2, *p_x2g, *p_a2,
         *p_idx2, *p_cnt2, *p_x2, *p_fi2, *p_pos3, *p_x3g, *p_a3,
         *p_idx3, *p_cnt3, *p_x3, *p_pm1, *p_pm2, *p_pm3,
         *p_w1, *p_w2, *p_w3;
    cudaGetSymbolAddress(&p_idx1, g_idx1);
    cudaGetSymbolAddress(&p_cnt1, g_cnt1);
    cudaGetSymbolAddress(&p_a1,   g_a1);
    cudaGetSymbolAddress(&p_x1,   g_x1);
    cudaGetSymbolAddress(&p_fi1,  g_fi1);
    cudaGetSymbolAddress(&p_pos2, g_pos2);
    cudaGetSymbolAddress(&p_x2g,  g_x2g);
    cudaGetSymbolAddress(&p_a2,   g_a2);
    cudaGetSymbolAddress(&p_idx2, g_idx2);
    cudaGetSymbolAddress(&p_cnt2, g_cnt2);
    cudaGetSymbolAddress(&p_x2,   g_x2);
    cudaGetSymbolAddress(&p_fi2,  g_fi2);
    cudaGetSymbolAddress(&p_pos3, g_pos3);
    cudaGetSymbolAddress(&p_x3g,  g_x3g);
    cudaGetSymbolAddress(&p_a3,   g_a3);
    cudaGetSymbolAddress(&p_idx3, g_idx3);
    cudaGetSymbolAddress(&p_cnt3, g_cnt3);
    cudaGetSymbolAddress(&p_x3,   g_x3);
    cudaGetSymbolAddress(&p_pm1,  g_perm1);
    cudaGetSymbolAddress(&p_pm2,  g_perm2);
    cudaGetSymbolAddress(&p_pm3,  g_perm3);
    cudaGetSymbolAddress(&p_w1,   g_w2t1);
    cudaGetSymbolAddress(&p_w2,   g_w2t2);
    cudaGetSymbolAddress(&p_w3,   g_w2t3);

    const int smMega1 = N1 * 12 + 256;                 // 49408
    const int smMega2 = N2 * 12 + 256;                 // 24832
    const int smKnn3  = 512 * 16;                      // 8192
    const int shc1 = 4 * (64 * 40 + 64)  * 4;          // 41984
    const int shc2 = 2 * (128 * 40 + 128) * 4;         // 41984
    const int shc3 = 1 * (256 * 40 + 256) * 4;         // 41984
    cudaFuncSetAttribute(mega_kernel<8>,
                         cudaFuncAttributeMaxDynamicSharedMemorySize, 50176);

    const float r1 = 0.2f, r2 = 0.4f, r3 = 1.0f;

    // W2 tf32 preconversion (cheap, once per launch)
    w2t_pre_kernel<64, 64><<<16, 256>>>(W1b, (u32*)p_w1);
    w2t_pre_kernel<128, 128><<<64, 256>>>(W2b, (u32*)p_w2);
    w2t_pre_kernel<256, 256><<<256, 256>>>(W3b, (u32*)p_w3);

    // level 1
    binsort_kernel<5><<<NB, 256>>>(pos, N1, (int*)p_pm1);
    node_pre_kernel<0, 64><<<(NB * N1 * 64) / 256, 256>>>(
        nullptr, pos, W1a, b1a, (float*)p_a1, NB * N1);
    mega_kernel<8><<<NB + (N1 / 512) * NB, 512, smMega1>>>(
        pos, r1 * r1, (int*)p_idx1, (int*)p_cnt1, N2, (int*)p_fi1, (int*)p_pm1);
    conv_mma_kernel<64, 64><<<dim3(N1 / 4, NB), 256, shc1>>>(
        (float*)p_a1, pos, (int*)p_idx1, (int*)p_cnt1,
        W1a, (u32*)p_w1, b1b, (float*)p_x1, N1);
    gather_kernel<<<256, 256>>>((float*)p_x1, pos, (int*)p_fi1,
                                (float*)p_x2g, (float*)p_pos2, N1, N2, 64);

    // level 2
    binsort_kernel<4><<<NB, 256>>>((float*)p_pos2, N2, (int*)p_pm2);
    node_pre_kernel<64, 128><<<(NB * N2 * 128) / 256, 256>>>(
        (float*)p_x2g, (float*)p_pos2, W2a, b2a, (float*)p_a2, NB * N2);
    mega_kernel<4><<<NB + (N2 / 512) * NB, 512, smMega2>>>(
        (float*)p_pos2, r2 * r2, (int*)p_idx2, (int*)p_cnt2, N3, (int*)p_fi2,
        (int*)p_pm2);
    conv_mma_kernel<128, 128><<<dim3(N2 / 2, NB), 256, shc2>>>(
        (float*)p_a2, (float*)p_pos2, (int*)p_idx2, (int*)p_cnt2,
        W2a + 64 * 128, (u32*)p_w2, b2b, (float*)p_x2, N2);
    gather_kernel<<<256, 256>>>((float*)p_x2, (float*)p_pos2, (int*)p_fi2,
                                (float*)p_x3g, (float*)p_pos3, N2, N3, 128);

    // level 3
    binsort_kernel<4><<<NB, 256>>>((float*)p_pos3, N3, (int*)p_pm3);
    node_pre_kernel<128, 256><<<(NB * N3 * 256) / 256, 256>>>(
        (float*)p_x3g, (float*)p_pos3, W3a, b3a, (float*)p_a3, NB * N3);
    knn_kernel<<<(N3 / 512) * NB, 512, smKnn3>>>(
        (float*)p_pos3, N3, r3 * r3, (int*)p_idx3, (int*)p_cnt3, (int*)p_pm3);
    conv_mma_kernel<256, 256><<<dim3(N3, NB), 256, shc3>>>(
        (float*)p_a3, (float*)p_pos3, (int*)p_idx3, (int*)p_cnt3,
        W3a + 128 * 256, (u32*)p_w3, b3b, (float*)p_x3, N3);

    // head
    head_kernel<<<NB, 256>>>((float*)p_x3, Wc1, bc1, Wc2, bc2, Wc3, bc3,
                             Wd1, bd1, Wd2, bd2, out);

    (void)in_sizes; (void)n_in; (void)out_size;
}

// round 12
// speedup vs baseline: 1.7519x; 1.0280x over previous
#include <cuda_runtime.h>
#include <math.h>
#include <float.h>

typedef unsigned int u32;

static constexpr int NB = 8, N1 = 4096, N2 = 2048, N3 = 512, KNN = 32;

// ---------------- scratch ----------------
__device__ int   g_idx1[NB * N1 * KNN];
__device__ int   g_cnt1[NB * N1];
__device__ float g_a1  [NB * N1 * 64];
__device__ float g_x1  [NB * N1 * 64];
__device__ int   g_fi1 [NB * N2];
__device__ float g_pos2[NB * N2 * 3];
__device__ float g_x2g [NB * N2 * 64];
__device__ float g_a2  [NB * N2 * 128];
__device__ int   g_idx2[NB * N2 * KNN];
__device__ int   g_cnt2[NB * N2];
__device__ float g_x2  [NB * N2 * 128];
__device__ int   g_fi2 [NB * N3];
__device__ float g_pos3[NB * N3 * 3];
__device__ float g_x3g [NB * N3 * 128];
__device__ float g_a3  [NB * N3 * 256];
__device__ int   g_idx3[NB * N3 * KNN];
__device__ int   g_cnt3[NB * N3];
__device__ float g_x3  [NB * N3 * 256];
__device__ int   g_perm1[NB * N1];
__device__ int   g_perm2[NB * N2];
__device__ int   g_perm3[NB * N3];
__device__ u32   g_w2t1[4096];
__device__ u32   g_w2t2[16384];
__device__ u32   g_w2t3[65536];

// ---------------- tf32 helpers ----------------
__device__ __forceinline__ u32 f2tf32(float f) {
    u32 r; asm("cvt.rna.tf32.f32 %0,%1;" : "=r"(r) : "f"(f)); return r;
}
__device__ __forceinline__ void mma_tf32(float* d, const u32* A, u32 b0, u32 b1) {
    asm("mma.sync.aligned.m16n8k8.row.col.f32.tf32.tf32.f32 "
        "{%0,%1,%2,%3},{%4,%5,%6,%7},{%8,%9},{%0,%1,%2,%3};"
        : "+f"(d[0]), "+f"(d[1]), "+f"(d[2]), "+f"(d[3])
        : "r"(A[0]), "r"(A[1]), "r"(A[2]), "r"(A[3]), "r"(b0), "r"(b1));
}

// ---------------- W2 -> tf32 fragment-major precompute ----------------
template <int CHID, int COUT>
__global__ void __launch_bounds__(256)
w2t_pre_kernel(const float* __restrict__ W2, u32* __restrict__ W2T)
{
    constexpr int NW = COUT / 32;
    int tid = blockIdx.x * 256 + threadIdx.x;
    int lane8 = tid & 255;
    int lane = lane8 >> 3, n = (lane8 & 7) >> 1, r = lane8 & 1;
    int rest = tid >> 8;
    int w = rest % NW, kt = rest / NW;
    int k = kt * 8 + (lane & 3) + r * 4;
    int c = w * 32 + n * 8 + (lane >> 2);
    W2T[tid] = f2tf32(W2[k * COUT + c]);
}

// ---------------- spatial counting sort ----------------
template <int NBIN>
__global__ void __launch_bounds__(256)
binsort_kernel(const float* __restrict__ pos, int N, int* __restrict__ perm)
{
    constexpr int B3 = NBIN * NBIN * NBIN;
    __shared__ int hist[B3];
    __shared__ int offs[B3];
    const int b = blockIdx.x, t = threadIdx.x;
    const float* pb = pos + (size_t)b * N * 3;

    for (int e = t; e < B3; e += 256) hist[e] = 0;
    __syncthreads();
    for (int i = t; i < N; i += 256) {
        int ix = min(NBIN - 1, max(0, (int)(pb[i * 3 + 0] * NBIN)));
        int iy = min(NBIN - 1, max(0, (int)(pb[i * 3 + 1] * NBIN)));
        int iz = min(NBIN - 1, max(0, (int)(pb[i * 3 + 2] * NBIN)));
        atomicAdd(&hist[(ix * NBIN + iy) * NBIN + iz], 1);
    }
    __syncthreads();
    if (t == 0) {
        int acc = 0;
        for (int k = 0; k < B3; ++k) { offs[k] = acc; acc += hist[k]; }
    }
    __syncthreads();
    for (int e = t; e < B3; e += 256) hist[e] = 0;
    __syncthreads();
    for (int i = t; i < N; i += 256) {
        int ix = min(NBIN - 1, max(0, (int)(pb[i * 3 + 0] * NBIN)));
        int iy = min(NBIN - 1, max(0, (int)(pb[i * 3 + 1] * NBIN)));
        int iz = min(NBIN - 1, max(0, (int)(pb[i * 3 + 2] * NBIN)));
        int key = (ix * NBIN + iy) * NBIN + iz;
        int r = offs[key] + atomicAdd(&hist[key], 1);
        perm[b * N + r] = i;
    }
}

// ---------------- per-node a_j = [x_j, pos_j] @ W1 + b1 ----------------
template <int CINX, int CHID>
__global__ void __launch_bounds__(256)
node_pre_kernel(const float* __restrict__ x, const float* __restrict__ pos,
                const float* __restrict__ W1, const float* __restrict__ b1,
                float* __restrict__ a, int nNodes)
{
    int tid = blockIdx.x * 256 + threadIdx.x;
    if (tid >= nNodes * CHID) return;
    int node = tid / CHID, c = tid - node * CHID;
    float acc = b1[c];
    if (CINX > 0) {
        const float* xr = x + (size_t)node * CINX;
#pragma unroll 4
        for (int f = 0; f < CINX; ++f)
            acc = fmaf(xr[f], W1[f * CHID + c], acc);
    }
    const float* pr = pos + (size_t)node * 3;
    acc = fmaf(pr[0], W1[(CINX + 0) * CHID + c], acc);
    acc = fmaf(pr[1], W1[(CINX + 1) * CHID + c], acc);
    acc = fmaf(pr[2], W1[(CINX + 2) * CHID + c], acc);
    a[tid] = acc;
}

// ---------------- KNN (512 thr), register top-32, bin-coherent queries ----
__device__ void knn_dev(const float* __restrict__ pb, int N, float r2v,
                        int* __restrict__ oidx, int* __restrict__ ocnt,
                        int qb, const int* __restrict__ perm, float4* sj)
{
    const int t = threadIdx.x;
    const int i = perm[qb * 512 + t];
    const float xi = pb[i * 3 + 0], yi = pb[i * 3 + 1], zi = pb[i * 3 + 2];
    const float sqi = __fadd_rn(__fadd_rn(__fmul_rn(xi, xi), __fmul_rn(yi, yi)),
                                __fmul_rn(zi, zi));
    const float m2x = -2.f * xi, m2y = -2.f * yi, m2z = -2.f * zi;

    float bd[KNN];
    int   bi_[KNN];
#pragma unroll
    for (int k = 0; k < KNN; ++k) { bd[k] = FLT_MAX; bi_[k] = 0; }
    float worst = FLT_MAX;

    for (int t0 = 0; t0 < N; t0 += 512) {
        __syncthreads();
        {
            int j = t0 + t;
            float x = pb[j * 3 + 0], y = pb[j * 3 + 1], z = pb[j * 3 + 2];
            float sq = __fadd_rn(__fadd_rn(__fmul_rn(x, x), __fmul_rn(y, y)),
                                 __fmul_rn(z, z));
            sj[t] = make_float4(x, y, z, sq);
        }
        __syncthreads();
#pragma unroll 2
        for (int jj = 0; jj < 512; ++jj) {
            float4 q = sj[jj];
            float d2 = sqi + fmaf(m2x, q.x, fmaf(m2y, q.y, fmaf(m2z, q.z, q.w)));
            int j = t0 + jj;
            if (d2 <= r2v && d2 < worst && j != i) {
#pragma unroll
                for (int k = KNN - 1; k > 0; --k) {
                    if (bd[k - 1] > d2)  { bd[k] = bd[k - 1]; bi_[k] = bi_[k - 1]; }
                    else if (bd[k] > d2) { bd[k] = d2;        bi_[k] = j; }
                }
                if (bd[0] > d2)          { bd[0] = d2;        bi_[0] = j; }
                worst = bd[KNN - 1];
            }
        }
    }
    int cnt = 0;
#pragma unroll
    for (int k = 0; k < KNN; ++k) cnt += (bd[k] <= r2v) ? 1 : 0;
    ocnt[i] = cnt;
    const int base = i * KNN;
#pragma unroll
    for (int k = 0; k < KNN; ++k) oidx[base + k] = bi_[k];
}

__global__ void __launch_bounds__(512, 1)
knn_kernel(const float* __restrict__ pos, int N, float r2v,
           int* __restrict__ oidx, int* __restrict__ ocnt,
           const int* __restrict__ perm)
{
    extern __shared__ char sm[];
    int b = blockIdx.x % NB, qb = blockIdx.x / NB;
    knn_dev(pos + (size_t)b * N * 3, N, r2v,
            oidx + (size_t)b * N * KNN, ocnt + b * N, qb,
            perm + b * N, (float4*)sm);
}

// ---------------- FPS (512 threads), standalone kernel -------------------
template <int P>
__global__ void __launch_bounds__(512, 1)
fps_kernel(const float* __restrict__ pos, int nS, int* __restrict__ fi)
{
    extern __shared__ char sm[];
    float* smf = (float*)sm;
    const int N = P * 512;
    const float* pb = pos + (size_t)blockIdx.x * N * 3;
    int* out = fi + blockIdx.x * nS;
    float* spos = smf;
    u32*  svb = (u32*)(smf + N * 3);  // [2][16]
    int*  si  = (int*)(svb + 32);     // [2][16]
    const int t = threadIdx.x, w = t >> 5, l = t & 31;

    for (int e = t; e < N * 3; e += 512) spos[e] = pb[e];
    __syncthreads();

    float px[P], py[P], pz[P], mind[P];
    const float x0 = spos[0], y0 = spos[1], z0 = spos[2];
    float bv = -1.f; int bidx = 0x7fffffff;
#pragma unroll
    for (int p = 0; p < P; ++p) {
        int i = t + p * 512;
        px[p] = spos[i * 3 + 0]; py[p] = spos[i * 3 + 1]; pz[p] = spos[i * 3 + 2];
        float dx = px[p] - x0, dy = py[p] - y0, dz = pz[p] - z0;
        mind[p] = __fadd_rn(__fadd_rn(__fmul_rn(dx, dx), __fmul_rn(dy, dy)),
                            __fmul_rn(dz, dz));
        if (mind[p] > bv) { bv = mind[p]; bidx = i; }
    }
    if (t == 0) out[0] = 0;

    int par = 0;
    for (int s = 1; s < nS; ++s) {
        u32 vb = __float_as_uint(bv);
        u32 m  = __reduce_max_sync(0xffffffffu, vb);
        u32 cand = (vb == m) ? (u32)bidx : 0xffffffffu;
        u32 wi = __reduce_min_sync(0xffffffffu, cand);
        if (l == 0) { svb[par * 16 + w] = m; si[par * 16 + w] = (int)wi; }
        __syncthreads();
        u32 v2 = (l < 16) ? svb[par * 16 + l] : 0u;
        u32 i2 = (l < 16) ? (u32)si[par * 16 + l] : 0xffffffffu;
        u32 m2 = __reduce_max_sync(0xffffffffu, v2);
        u32 c2 = (v2 == m2 && l < 16) ? i2 : 0xffffffffu;
        u32 gi = __reduce_min_sync(0xffffffffu, c2);
        if (t == 0) out[s] = (int)gi;
        const float cx = spos[gi * 3 + 0];
        const float cy = spos[gi * 3 + 1];
        const float cz = spos[gi * 3 + 2];
        par ^= 1;
        bv = -1.f; bidx = 0x7fffffff;
#pragma unroll
        for (int p = 0; p < P; ++p) {
            float dx = px[p] - cx, dy = py[p] - cy, dz = pz[p] - cz;
            float d = __fadd_rn(__fadd_rn(__fmul_rn(dx, dx), __fmul_rn(dy, dy)),
                                __fmul_rn(dz, dz));
            mind[p] = fminf(mind[p], d);
            if (mind[p] > bv) { bv = mind[p]; bidx = t + p * 512; }
        }
    }
}

// ---------------- gather after FPS ----------------
__global__ void gather_kernel(const float* __restrict__ xin,
                              const float* __restrict__ posin,
                              const int* __restrict__ fi,
                              float* __restrict__ xo, float* __restrict__ poso,
                              int Nin, int Nout, int C)
{
    const int tid = blockIdx.x * blockDim.x + threadIdx.x;
    const int stride = gridDim.x * blockDim.x;
    const int totX = NB * Nout * C;
    for (int e = tid; e < totX; e += stride) {
        int c = e % C, m = (e / C) % Nout, b = e / (C * Nout);
        int j = fi[b * Nout + m];
        xo[e] = xin[((size_t)b * Nin + j) * C + c];
    }
    const int totP = NB * Nout * 3;
    for (int e = tid; e < totP; e += stride) {
        int d = e % 3, m = (e / 3) % Nout, b = e / (3 * Nout);
        int j = fi[b * Nout + m];
        poso[e] = posin[((size_t)b * Nin + j) * 3 + d];
    }
}

// ---------------- PointNetConv on tensor cores (tf32, preconverted W) ----
template <int CHID, int COUT>
__global__ void __launch_bounds__(256)
conv_mma_kernel(const float* __restrict__ a, const float* __restrict__ pos,
                const int* __restrict__ kidx, const int* __restrict__ kcnt,
                const float* __restrict__ W1p, const u32* __restrict__ W2T,
                const float* __restrict__ b2, float* __restrict__ xout, int N)
{
    constexpr int NW  = COUT / 32;
    constexpr int TPG = COUT;
    constexpr int PPB = 256 / TPG;
    constexpr int KT  = CHID / 8;
    constexpr int HS  = 40;
    constexpr int GSZ = CHID * HS + CHID;
    extern __shared__ char sm[];
    float* smem = (float*)sm;
    const int tg = threadIdx.x / TPG;
    const int tp = threadIdx.x % TPG;
    u32*   hTu = (u32*)(smem + tg * GSZ);
    float* scv = smem + tg * GSZ + CHID * HS;
    __shared__ int   sidx[PPB][KNN];
    __shared__ float spi[PPB][3];
    __shared__ int   scnt[PPB];

    const int b = blockIdx.y;
    const int i = blockIdx.x * PPB + tg;

    if (tp < KNN) sidx[tg][tp] = kidx[((size_t)b * N + i) * KNN + tp];
    if (tp == 0)  scnt[tg] = kcnt[b * N + i];
    if (tp < 3)   spi[tg][tp] = pos[((size_t)b * N + i) * 3 + tp];
    __syncthreads();
    const int cnt = scnt[tg];
    const float p0 = spi[tg][0], p1 = spi[tg][1], p2 = spi[tg][2];
    scv[tp] = fmaf(p2, W1p[2 * CHID + tp],
                   fmaf(p1, W1p[CHID + tp], p0 * W1p[tp]));
    __syncthreads();

    const float* ab = a + (size_t)b * N * CHID;
    const float cv = scv[tp];
#pragma unroll
    for (int kq = 0; kq < 8; ++kq) {
        int j0 = sidx[tg][kq * 4 + 0], j1 = sidx[tg][kq * 4 + 1];
        int j2 = sidx[tg][kq * 4 + 2], j3 = sidx[tg][kq * 4 + 3];
        uint4 h;
        h.x = f2tf32(fmaxf(ab[(size_t)j0 * CHID + tp] - cv, 0.f));
        h.y = f2tf32(fmaxf(ab[(size_t)j1 * CHID + tp] - cv, 0.f));
        h.z = f2tf32(fmaxf(ab[(size_t)j2 * CHID + tp] - cv, 0.f));
        h.w = f2tf32(fmaxf(ab[(size_t)j3 * CHID + tp] - cv, 0.f));
        *(uint4*)&hTu[tp * HS + kq * 4] = h;
    }
    __syncthreads();

    const int lane = tp & 31;
    const int w = tp >> 5;
    const int q = lane >> 2, kk = lane & 3;
    const uint4* Wt = (const uint4*)W2T;

    float d[2][4][4];
#pragma unroll
    for (int m = 0; m < 2; ++m)
#pragma unroll
        for (int n = 0; n < 4; ++n)
#pragma unroll
            for (int r = 0; r < 4; ++r) d[m][n][r] = 0.f;

    for (int kt = 0; kt < KT; ++kt) {
        const u32* col0 = hTu + (kt * 8 + kk) * HS;
        const u32* col4 = col0 + 4 * HS;
        u32 A0[4], A1[4];
        A0[0] = col0[q];       A0[1] = col0[q + 8];
        A0[2] = col4[q];       A0[3] = col4[q + 8];
        A1[0] = col0[16 + q];  A1[1] = col0[16 + q + 8];
        A1[2] = col4[16 + q];  A1[3] = col4[16 + q + 8];
        uint4 B0 = Wt[((kt * NW + w) * 32 + lane) * 2 + 0];
        uint4 B1 = Wt[((kt * NW + w) * 32 + lane) * 2 + 1];
        mma_tf32(d[0][0], A0, B0.x, B0.y);
        mma_tf32(d[0][1], A0, B0.z, B0.w);
        mma_tf32(d[0][2], A0, B1.x, B1.y);
        mma_tf32(d[0][3], A0, B1.z, B1.w);
        mma_tf32(d[1][0], A1, B0.x, B0.y);
        mma_tf32(d[1][1], A1, B0.z, B0.w);
        mma_tf32(d[1][2], A1, B1.x, B1.y);
        mma_tf32(d[1][3], A1, B1.z, B1.w);
    }

#pragma unroll
    for (int n = 0; n < 4; ++n) {
        float v0 = -FLT_MAX, v1 = -FLT_MAX;
#pragma unroll
        for (int m = 0; m < 2; ++m) {
            int r0 = m * 16 + q, r1 = r0 + 8;
            if (r0 < cnt) { v0 = fmaxf(v0, d[m][n][0]); v1 = fmaxf(v1, d[m][n][1]); }
            if (r1 < cnt) { v0 = fmaxf(v0, d[m][n][2]); v1 = fmaxf(v1, d[m][n][3]); }
        }
        v0 = fmaxf(v0, __shfl_xor_sync(0xffffffffu, v0, 4));
        v1 = fmaxf(v1, __shfl_xor_sync(0xffffffffu, v1, 4));
        v0 = fmaxf(v0, __shfl_xor_sync(0xffffffffu, v0, 8));
        v1 = fmaxf(v1, __shfl_xor_sync(0xffffffffu, v1, 8));
        v0 = fmaxf(v0, __shfl_xor_sync(0xffffffffu, v0, 16));
        v1 = fmaxf(v1, __shfl_xor_sync(0xffffffffu, v1, 16));
        if (lane < 4) {
            int c = w * 32 + n * 8 + lane * 2;
            float o0 = (cnt > 0) ? fmaxf(v0 + b2[c], 0.f) : 0.f;
            float o1 = (cnt > 0) ? fmaxf(v1 + b2[c + 1], 0.f) : 0.f;
            xout[((size_t)b * N + i) * COUT + c]     = o0;
            xout[((size_t)b * N + i) * COUT + c + 1] = o1;
        }
    }
}

// ---------------- head ----------------
__global__ void head_kernel(const float* __restrict__ x3,
                            const float* __restrict__ Wc1, const float* __restrict__ bc1,
                            const float* __restrict__ Wc2, const float* __restrict__ bc2,
                            const float* __restrict__ Wc3, const float* __restrict__ bc3,
                            const float* __restrict__ Wd1, const float* __restrict__ bd1,
                            const float* __restrict__ Wd2, const float* __restrict__ bd2,
                            float* __restrict__ out)
{
    __shared__ float sf[256], sh[256], sh2[256], slog[40], sd[2];
    const int b = blockIdx.x, t = threadIdx.x;

    float m = -FLT_MAX;
    for (int n = 0; n < N3; ++n)
        m = fmaxf(m, x3[((size_t)b * N3 + n) * 256 + t]);
    sf[t] = m;
    __syncthreads();

    float a = bc1[t];
    for (int c = 0; c < 256; ++c) a = fmaf(sf[c], Wc1[c * 256 + t], a);
    sh[t] = fmaxf(a, 0.f);
    __syncthreads();

    a = bc2[t];
    for (int c = 0; c < 256; ++c) a = fmaf(sh[c], Wc2[c * 256 + t], a);
    sh2[t] = fmaxf(a, 0.f);
    __syncthreads();

    if (t < 40) {
        float l = bc3[t];
        for (int c = 0; c < 256; ++c) l = fmaf(sh2[c], Wc3[c * 40 + t], l);
        slog[t] = l;
    }
    float a2 = bd1[t];
    for (int c = 0; c < 256; ++c) a2 = fmaf(sf[c], Wd1[c * 256 + t], a2);
    a2 = fmaxf(a2, 0.f);
    __syncthreads();
    sh[t] = a2;
    __syncthreads();
    if (t < 2) {
        float l = bd2[t];
        for (int c = 0; c < 256; ++c) l = fmaf(sh[c], Wd2[c * 2 + t], l);
        sd[t] = l;
    }
    __syncthreads();

    if (t < 40) {
        float mx = -FLT_MAX;
        for (int j = 0; j < 40; ++j) mx = fmaxf(mx, slog[j]);
        float se = 0.f;
        for (int j = 0; j < 40; ++j) se += expf(slog[j] - mx);
        out[b * 40 + t] = slog[t] - mx - logf(se);
    }
    if (t < 2) {
        float mx = fmaxf(sd[0], sd[1]);
        float se = expf(sd[0] - mx) + expf(sd[1] - mx);
        out[NB * 40 + b * 2 + t] = sd[t] - mx - logf(se);
    }
}

// ---------------- stream/event singletons (host objects, created at load) --
static cudaStream_t g_s2;
static cudaEvent_t g_evf1, g_evj1, g_evf2, g_evj2;
static bool g_init = []() {
    cudaStreamCreateWithFlags(&g_s2, cudaStreamNonBlocking);
    cudaEventCreateWithFlags(&g_evf1, cudaEventDisableTiming);
    cudaEventCreateWithFlags(&g_evj1, cudaEventDisableTiming);
    cudaEventCreateWithFlags(&g_evf2, cudaEventDisableTiming);
    cudaEventCreateWithFlags(&g_evj2, cudaEventDisableTiming);
    return true;
}();

// ---------------- launch ----------------
extern "C" void kernel_launch(void* const* d_in, const int* in_sizes, int n_in,
                              void* d_out, int out_size)
{
    const float* pos = (const float*)d_in[0];
    const float* W1a = (const float*)d_in[1];  const float* b1a = (const float*)d_in[2];
    const float* W1b = (const float*)d_in[3];  const float* b1b = (const float*)d_in[4];
    const float* W2a = (const float*)d_in[5];  const float* b2a = (const float*)d_in[6];
    const float* W2b = (const float*)d_in[7];  const float* b2b = (const float*)d_in[8];
    const float* W3a = (const float*)d_in[9];  const float* b3a = (const float*)d_in[10];
    const float* W3b = (const float*)d_in[11]; const float* b3b = (const float*)d_in[12];
    const float* Wc1 = (const float*)d_in[13]; const float* bc1 = (const float*)d_in[14];
    const float* Wc2 = (const float*)d_in[15]; const float* bc2 = (const float*)d_in[16];
    const float* Wc3 = (const float*)d_in[17]; const float* bc3 = (const float*)d_in[18];
    const float* Wd1 = (const float*)d_in[19]; const float* bd1 = (const float*)d_in[20];
    const float* Wd2 = (const float*)d_in[21]; const float* bd2 = (const float*)d_in[22];
    float* out = (float*)d_out;

    void *p_idx1, *p_cnt1, *p_a1, *p_x1, *p_fi1, *p_pos2, *p_x2g, *p_a2,
         *p_idx2, *p_cnt2, *p_x2, *p_fi2, *p_pos3, *p_x3g, *p_a3,
         *p_idx3, *p_cnt3, *p_x3, *p_pm1, *p_pm2, *p_pm3,
         *p_w1, *p_w2, *p_w3;
    cudaGetSymbolAddress(&p_idx1, g_idx1);
    cudaGetSymbolAddress(&p_cnt1, g_cnt1);
    cudaGetSymbolAddress(&p_a1,   g_a1);
    cudaGetSymbolAddress(&p_x1,   g_x1);
    cudaGetSymbolAddress(&p_fi1,  g_fi1);
    cudaGetSymbolAddress(&p_pos2, g_pos2);
    cudaGetSymbolAddress(&p_x2g,  g_x2g);
    cudaGetSymbolAddress(&p_a2,   g_a2);
    cudaGetSymbolAddress(&p_idx2, g_idx2);
    cudaGetSymbolAddress(&p_cnt2, g_cnt2);
    cudaGetSymbolAddress(&p_x2,   g_x2);
    cudaGetSymbolAddress(&p_fi2,  g_fi2);
    cudaGetSymbolAddress(&p_pos3, g_pos3);
    cudaGetSymbolAddress(&p_x3g,  g_x3g);
    cudaGetSymbolAddress(&p_a3,   g_a3);
    cudaGetSymbolAddress(&p_idx3, g_idx3);
    cudaGetSymbolAddress(&p_cnt3, g_cnt3);
    cudaGetSymbolAddress(&p_x3,   g_x3);
    cudaGetSymbolAddress(&p_pm1,  g_perm1);
    cudaGetSymbolAddress(&p_pm2,  g_perm2);
    cudaGetSymbolAddress(&p_pm3,  g_perm3);
    cudaGetSymbolAddress(&p_w1,   g_w2t1);
    cudaGetSymbolAddress(&p_w2,   g_w2t2);
    cudaGetSymbolAddress(&p_w3,   g_w2t3);

    const int smFps1 = N1 * 12 + 256;                  // 49408 > 48K
    const int smFps2 = N2 * 12 + 256;                  // 24832
    const int smKnn  = 512 * 16;                       // 8192
    const int shc1 = 4 * (64 * 40 + 64)  * 4;          // 41984
    const int shc2 = 2 * (128 * 40 + 128) * 4;         // 41984
    const int shc3 = 1 * (256 * 40 + 256) * 4;         // 41984
    cudaFuncSetAttribute(fps_kernel<8>,
                         cudaFuncAttributeMaxDynamicSharedMemorySize, 50176);

    const float r1 = 0.2f, r2 = 0.4f, r3 = 1.0f;

    // ---- level 1 ----
    binsort_kernel<5><<<NB, 256>>>(pos, N1, (int*)p_pm1);

    // fork: FPS1 on side stream; KNN1/conv1 chain on main stream
    cudaEventRecord(g_evf1, 0);
    cudaStreamWaitEvent(g_s2, g_evf1, 0);
    fps_kernel<8><<<NB, 512, smFps1, g_s2>>>(pos, N2, (int*)p_fi1);

    w2t_pre_kernel<64, 64><<<16, 256>>>(W1b, (u32*)p_w1);
    w2t_pre_kernel<128, 128><<<64, 256>>>(W2b, (u32*)p_w2);
    w2t_pre_kernel<256, 256><<<256, 256>>>(W3b, (u32*)p_w3);
    node_pre_kernel<0, 64><<<(NB * N1 * 64) / 256, 256>>>(
        nullptr, pos, W1a, b1a, (float*)p_a1, NB * N1);
    knn_kernel<<<(N1 / 512) * NB, 512, smKnn>>>(
        pos, N1, r1 * r1, (int*)p_idx1, (int*)p_cnt1, (int*)p_pm1);
    conv_mma_kernel<64, 64><<<dim3(N1 / 4, NB), 256, shc1>>>(
        (float*)p_a1, pos, (int*)p_idx1, (int*)p_cnt1,
        W1a, (u32*)p_w1, b1b, (float*)p_x1, N1);

    // join: gather needs fi1 (fps1) + x1 (conv1)
    cudaEventRecord(g_evj1, g_s2);
    cudaStreamWaitEvent(0, g_evj1, 0);
    gather_kernel<<<256, 256>>>((float*)p_x1, pos, (int*)p_fi1,
                                (float*)p_x2g, (float*)p_pos2, N1, N2, 64);

    // ---- level 2 ----
    binsort_kernel<4><<<NB, 256>>>((float*)p_pos2, N2, (int*)p_pm2);

    cudaEventRecord(g_evf2, 0);
    cudaStreamWaitEvent(g_s2, g_evf2, 0);
    fps_kernel<4><<<NB, 512, smFps2, g_s2>>>((float*)p_pos2, N3, (int*)p_fi2);

    node_pre_kernel<64, 128><<<(NB * N2 * 128) / 256, 256>>>(
        (float*)p_x2g, (float*)p_pos2, W2a, b2a, (float*)p_a2, NB * N2);
    knn_kernel<<<(N2 / 512) * NB, 512, smKnn>>>(
        (float*)p_pos2, N2, r2 * r2, (int*)p_idx2, (int*)p_cnt2, (int*)p_pm2);
    conv_mma_kernel<128, 128><<<dim3(N2 / 2, NB), 256, shc2>>>(
        (float*)p_a2, (float*)p_pos2, (int*)p_idx2, (int*)p_cnt2,
        W2a + 64 * 128, (u32*)p_w2, b2b, (float*)p_x2, N2);

    cudaEventRecord(g_evj2, g_s2);
    cudaStreamWaitEvent(0, g_evj2, 0);
    gather_kernel<<<256, 256>>>((float*)p_x2, (float*)p_pos2, (int*)p_fi2,
                                (float*)p_x3g, (float*)p_pos3, N2, N3, 128);

    // ---- level 3 ----
    binsort_kernel<4><<<NB, 256>>>((float*)p_pos3, N3, (int*)p_pm3);
    node_pre_kernel<128, 256><<<(NB * N3 * 256) / 256, 256>>>(
        (float*)p_x3g, (float*)p_pos3, W3a, b3a, (float*)p_a3, NB * N3);
    knn_kernel<<<(N3 / 512) * NB, 512, smKnn>>>(
        (float*)p_pos3, N3, r3 * r3, (int*)p_idx3, (int*)p_cnt3, (int*)p_pm3);
    conv_mma_kernel<256, 256><<<dim3(N3, NB), 256, shc3>>>(
        (float*)p_a3, (float*)p_pos3, (int*)p_idx3, (int*)p_cnt3,
        W3a + 128 * 256, (u32*)p_w3, b3b, (float*)p_x3, N3);

    // head
    head_kernel<<<NB, 256>>>((float*)p_x3, Wc1, bc1, Wc2, bc2, Wc3, bc3,
                             Wd1, bd1, Wd2, bd2, out);

    (void)in_sizes; (void)n_in; (void)out_size; (void)g_init;
}

// round 13
// speedup vs baseline: 1.7589x; 1.0040x over previous
#include <cuda_runtime.h>
#include <math.h>
#include <float.h>

typedef unsigned int u32;

static constexpr int NB = 8, N1 = 4096, N2 = 2048, N3 = 512, KNN = 32;

// ---------------- scratch ----------------
__device__ int   g_idx1[NB * N1 * KNN];
__device__ int   g_cnt1[NB * N1];
__device__ float g_a1  [NB * N1 * 64];
__device__ float g_x1  [NB * N1 * 64];
__device__ int   g_fi1 [NB * N2];
__device__ float g_pos2[NB * N2 * 3];
__device__ float g_x2g [NB * N2 * 64];
__device__ float g_a2  [NB * N2 * 128];
__device__ int   g_idx2[NB * N2 * KNN];
__device__ int   g_cnt2[NB * N2];
__device__ float g_x2  [NB * N2 * 128];
__device__ int   g_fi2 [NB * N3];
__device__ float g_pos3[NB * N3 * 3];
__device__ float g_x3g [NB * N3 * 128];
__device__ float g_a3  [NB * N3 * 256];
__device__ int   g_idx3[NB * N3 * KNN];
__device__ int   g_cnt3[NB * N3];
__device__ float g_x3  [NB * N3 * 256];
__device__ int   g_perm1[NB * N1];
__device__ int   g_perm2[NB * N2];
__device__ int   g_perm3[NB * N3];
__device__ u32   g_w2t1[4096];
__device__ u32   g_w2t2[16384];
__device__ u32   g_w2t3[65536];

// ---------------- tf32 helpers ----------------
__device__ __forceinline__ u32 f2tf32(float f) {
    u32 r; asm("cvt.rna.tf32.f32 %0,%1;" : "=r"(r) : "f"(f)); return r;
}
__device__ __forceinline__ void mma_tf32(float* d, const u32* A, u32 b0, u32 b1) {
    asm("mma.sync.aligned.m16n8k8.row.col.f32.tf32.tf32.f32 "
        "{%0,%1,%2,%3},{%4,%5,%6,%7},{%8,%9},{%0,%1,%2,%3};"
        : "+f"(d[0]), "+f"(d[1]), "+f"(d[2]), "+f"(d[3])
        : "r"(A[0]), "r"(A[1]), "r"(A[2]), "r"(A[3]), "r"(b0), "r"(b1));
}

// ---------------- W2 -> tf32 fragment-major precompute ----------------
template <int CHID, int COUT>
__global__ void __launch_bounds__(256)
w2t_pre_kernel(const float* __restrict__ W2, u32* __restrict__ W2T)
{
    constexpr int NW = COUT / 32;
    int tid = blockIdx.x * 256 + threadIdx.x;
    int lane8 = tid & 255;
    int lane = lane8 >> 3, n = (lane8 & 7) >> 1, r = lane8 & 1;
    int rest = tid >> 8;
    int w = rest % NW, kt = rest / NW;
    int k = kt * 8 + (lane & 3) + r * 4;
    int c = w * 32 + n * 8 + (lane >> 2);
    W2T[tid] = f2tf32(W2[k * COUT + c]);
}

// ---------------- spatial counting sort ----------------
template <int NBIN>
__global__ void __launch_bounds__(256)
binsort_kernel(const float* __restrict__ pos, int N, int* __restrict__ perm)
{
    constexpr int B3 = NBIN * NBIN * NBIN;
    __shared__ int hist[B3];
    __shared__ int offs[B3];
    const int b = blockIdx.x, t = threadIdx.x;
    const float* pb = pos + (size_t)b * N * 3;

    for (int e = t; e < B3; e += 256) hist[e] = 0;
    __syncthreads();
    for (int i = t; i < N; i += 256) {
        int ix = min(NBIN - 1, max(0, (int)(pb[i * 3 + 0] * NBIN)));
        int iy = min(NBIN - 1, max(0, (int)(pb[i * 3 + 1] * NBIN)));
        int iz = min(NBIN - 1, max(0, (int)(pb[i * 3 + 2] * NBIN)));
        atomicAdd(&hist[(ix * NBIN + iy) * NBIN + iz], 1);
    }
    __syncthreads();
    if (t == 0) {
        int acc = 0;
        for (int k = 0; k < B3; ++k) { offs[k] = acc; acc += hist[k]; }
    }
    __syncthreads();
    for (int e = t; e < B3; e += 256) hist[e] = 0;
    __syncthreads();
    for (int i = t; i < N; i += 256) {
        int ix = min(NBIN - 1, max(0, (int)(pb[i * 3 + 0] * NBIN)));
        int iy = min(NBIN - 1, max(0, (int)(pb[i * 3 + 1] * NBIN)));
        int iz = min(NBIN - 1, max(0, (int)(pb[i * 3 + 2] * NBIN)));
        int key = (ix * NBIN + iy) * NBIN + iz;
        int r = offs[key] + atomicAdd(&hist[key], 1);
        perm[b * N + r] = i;
    }
}

// ---------------- per-node a_j = [x_j, pos_j] @ W1 + b1 ----------------
template <int CINX, int CHID>
__global__ void __launch_bounds__(256)
node_pre_kernel(const float* __restrict__ x, const float* __restrict__ pos,
                const float* __restrict__ W1, const float* __restrict__ b1,
                float* __restrict__ a, int nNodes)
{
    int tid = blockIdx.x * 256 + threadIdx.x;
    if (tid >= nNodes * CHID) return;
    int node = tid / CHID, c = tid - node * CHID;
    float acc = b1[c];
    if (CINX > 0) {
        const float* xr = x + (size_t)node * CINX;
#pragma unroll 4
        for (int f = 0; f < CINX; ++f)
            acc = fmaf(xr[f], W1[f * CHID + c], acc);
    }
    const float* pr = pos + (size_t)node * 3;
    acc = fmaf(pr[0], W1[(CINX + 0) * CHID + c], acc);
    acc = fmaf(pr[1], W1[(CINX + 1) * CHID + c], acc);
    acc = fmaf(pr[2], W1[(CINX + 2) * CHID + c], acc);
    a[tid] = acc;
}

// ---------------- KNN (512 thr), register top-32, bin-coherent queries ----
__device__ void knn_dev(const float* __restrict__ pb, int N, float r2v,
                        int* __restrict__ oidx, int* __restrict__ ocnt,
                        int qb, const int* __restrict__ perm, float4* sj)
{
    const int t = threadIdx.x;
    const int i = perm[qb * 512 + t];
    const float xi = pb[i * 3 + 0], yi = pb[i * 3 + 1], zi = pb[i * 3 + 2];
    const float sqi = __fadd_rn(__fadd_rn(__fmul_rn(xi, xi), __fmul_rn(yi, yi)),
                                __fmul_rn(zi, zi));
    const float m2x = -2.f * xi, m2y = -2.f * yi, m2z = -2.f * zi;

    float bd[KNN];
    int   bi_[KNN];
#pragma unroll
    for (int k = 0; k < KNN; ++k) { bd[k] = FLT_MAX; bi_[k] = 0; }
    float worst = FLT_MAX;

    for (int t0 = 0; t0 < N; t0 += 512) {
        __syncthreads();
        {
            int j = t0 + t;
            float x = pb[j * 3 + 0], y = pb[j * 3 + 1], z = pb[j * 3 + 2];
            float sq = __fadd_rn(__fadd_rn(__fmul_rn(x, x), __fmul_rn(y, y)),
                                 __fmul_rn(z, z));
            sj[t] = make_float4(x, y, z, sq);
        }
        __syncthreads();
#pragma unroll 2
        for (int jj = 0; jj < 512; ++jj) {
            float4 q = sj[jj];
            float d2 = sqi + fmaf(m2x, q.x, fmaf(m2y, q.y, fmaf(m2z, q.z, q.w)));
            int j = t0 + jj;
            if (d2 <= r2v && d2 < worst && j != i) {
#pragma unroll
                for (int k = KNN - 1; k > 0; --k) {
                    if (bd[k - 1] > d2)  { bd[k] = bd[k - 1]; bi_[k] = bi_[k - 1]; }
                    else if (bd[k] > d2) { bd[k] = d2;        bi_[k] = j; }
                }
                if (bd[0] > d2)          { bd[0] = d2;        bi_[0] = j; }
                worst = bd[KNN - 1];
            }
        }
    }
    int cnt = 0;
#pragma unroll
    for (int k = 0; k < KNN; ++k) cnt += (bd[k] <= r2v) ? 1 : 0;
    ocnt[i] = cnt;
    const int base = i * KNN;
#pragma unroll
    for (int k = 0; k < KNN; ++k) oidx[base + k] = bi_[k];
}

__global__ void __launch_bounds__(512, 1)
knn_kernel(const float* __restrict__ pos, int N, float r2v,
           int* __restrict__ oidx, int* __restrict__ ocnt,
           const int* __restrict__ perm)
{
    extern __shared__ char sm[];
    int b = blockIdx.x % NB, qb = blockIdx.x / NB;
    knn_dev(pos + (size_t)b * N * 3, N, r2v,
            oidx + (size_t)b * N * KNN, ocnt + b * N, qb,
            perm + b * N, (float4*)sm);
}

// ---------------- FPS (512 threads), standalone kernel -------------------
template <int P>
__global__ void __launch_bounds__(512, 1)
fps_kernel(const float* __restrict__ pos, int nS, int* __restrict__ fi)
{
    extern __shared__ char sm[];
    float* smf = (float*)sm;
    const int N = P * 512;
    const float* pb = pos + (size_t)blockIdx.x * N * 3;
    int* out = fi + blockIdx.x * nS;
    float* spos = smf;
    u32*  svb = (u32*)(smf + N * 3);  // [2][16]
    int*  si  = (int*)(svb + 32);     // [2][16]
    const int t = threadIdx.x, w = t >> 5, l = t & 31;

    for (int e = t; e < N * 3; e += 512) spos[e] = pb[e];
    __syncthreads();

    float px[P], py[P], pz[P], mind[P];
    const float x0 = spos[0], y0 = spos[1], z0 = spos[2];
    float bv = -1.f; int bidx = 0x7fffffff;
#pragma unroll
    for (int p = 0; p < P; ++p) {
        int i = t + p * 512;
        px[p] = spos[i * 3 + 0]; py[p] = spos[i * 3 + 1]; pz[p] = spos[i * 3 + 2];
        float dx = px[p] - x0, dy = py[p] - y0, dz = pz[p] - z0;
        mind[p] = __fadd_rn(__fadd_rn(__fmul_rn(dx, dx), __fmul_rn(dy, dy)),
                            __fmul_rn(dz, dz));
        if (mind[p] > bv) { bv = mind[p]; bidx = i; }
    }
    if (t == 0) out[0] = 0;

    int par = 0;
    for (int s = 1; s < nS; ++s) {
        u32 vb = __float_as_uint(bv);
        u32 m  = __reduce_max_sync(0xffffffffu, vb);
        u32 cand = (vb == m) ? (u32)bidx : 0xffffffffu;
        u32 wi = __reduce_min_sync(0xffffffffu, cand);
        if (l == 0) { svb[par * 16 + w] = m; si[par * 16 + w] = (int)wi; }
        __syncthreads();
        u32 v2 = (l < 16) ? svb[par * 16 + l] : 0u;
        u32 i2 = (l < 16) ? (u32)si[par * 16 + l] : 0xffffffffu;
        u32 m2 = __reduce_max_sync(0xffffffffu, v2);
        u32 c2 = (v2 == m2 && l < 16) ? i2 : 0xffffffffu;
        u32 gi = __reduce_min_sync(0xffffffffu, c2);
        if (t == 0) out[s] = (int)gi;
        const float cx = spos[gi * 3 + 0];
        const float cy = spos[gi * 3 + 1];
        const float cz = spos[gi * 3 + 2];
        par ^= 1;
        bv = -1.f; bidx = 0x7fffffff;
#pragma unroll
        for (int p = 0; p < P; ++p) {
            float dx = px[p] - cx, dy = py[p] - cy, dz = pz[p] - cz;
            float d = __fadd_rn(__fadd_rn(__fmul_rn(dx, dx), __fmul_rn(dy, dy)),
                                __fmul_rn(dz, dz));
            mind[p] = fminf(mind[p], d);
            if (mind[p] > bv) { bv = mind[p]; bidx = t + p * 512; }
        }
    }
}

// ---------------- pos-only gather (runs on FPS stream; needs only pos+fi) -
__global__ void posgather_kernel(const float* __restrict__ posin,
                                 const int* __restrict__ fi,
                                 float* __restrict__ poso, int Nin, int Nout)
{
    const int tid = blockIdx.x * blockDim.x + threadIdx.x;
    const int tot = NB * Nout * 3;
    if (tid >= tot) return;
    int d = tid % 3, m = (tid / 3) % Nout, b = tid / (3 * Nout);
    int j = fi[b * Nout + m];
    poso[tid] = posin[((size_t)b * Nin + j) * 3 + d];
}

// ---------------- feature gather (main stream; needs conv output) --------
__global__ void xgather_kernel(const float* __restrict__ xin,
                               const int* __restrict__ fi,
                               float* __restrict__ xo, int Nin, int Nout, int C)
{
    const int tid = blockIdx.x * blockDim.x + threadIdx.x;
    const int stride = gridDim.x * blockDim.x;
    const int tot = NB * Nout * C;
    for (int e = tid; e < tot; e += stride) {
        int c = e % C, m = (e / C) % Nout, b = e / (C * Nout);
        int j = fi[b * Nout + m];
        xo[e] = xin[((size_t)b * Nin + j) * C + c];
    }
}

// ---------------- PointNetConv on tensor cores (tf32, preconverted W) ----
template <int CHID, int COUT>
__global__ void __launch_bounds__(256)
conv_mma_kernel(const float* __restrict__ a, const float* __restrict__ pos,
                const int* __restrict__ kidx, const int* __restrict__ kcnt,
                const float* __restrict__ W1p, const u32* __restrict__ W2T,
                const float* __restrict__ b2, float* __restrict__ xout, int N)
{
    constexpr int NW  = COUT / 32;
    constexpr int TPG = COUT;
    constexpr int PPB = 256 / TPG;
    constexpr int KT  = CHID / 8;
    constexpr int HS  = 40;
    constexpr int GSZ = CHID * HS + CHID;
    extern __shared__ char sm[];
    float* smem = (float*)sm;
    const int tg = threadIdx.x / TPG;
    const int tp = threadIdx.x % TPG;
    u32*   hTu = (u32*)(smem + tg * GSZ);
    float* scv = smem + tg * GSZ + CHID * HS;
    __shared__ int   sidx[PPB][KNN];
    __shared__ float spi[PPB][3];
    __shared__ int   scnt[PPB];

    const int b = blockIdx.y;
    const int i = blockIdx.x * PPB + tg;

    if (tp < KNN) sidx[tg][tp] = kidx[((size_t)b * N + i) * KNN + tp];
    if (tp == 0)  scnt[tg] = kcnt[b * N + i];
    if (tp < 3)   spi[tg][tp] = pos[((size_t)b * N + i) * 3 + tp];
    __syncthreads();
    const int cnt = scnt[tg];
    const float p0 = spi[tg][0], p1 = spi[tg][1], p2 = spi[tg][2];
    scv[tp] = fmaf(p2, W1p[2 * CHID + tp],
                   fmaf(p1, W1p[CHID + tp], p0 * W1p[tp]));
    __syncthreads();

    const float* ab = a + (size_t)b * N * CHID;
    const float cv = scv[tp];
#pragma unroll
    for (int kq = 0; kq < 8; ++kq) {
        int j0 = sidx[tg][kq * 4 + 0], j1 = sidx[tg][kq * 4 + 1];
        int j2 = sidx[tg][kq * 4 + 2], j3 = sidx[tg][kq * 4 + 3];
        uint4 h;
        h.x = f2tf32(fmaxf(ab[(size_t)j0 * CHID + tp] - cv, 0.f));
        h.y = f2tf32(fmaxf(ab[(size_t)j1 * CHID + tp] - cv, 0.f));
        h.z = f2tf32(fmaxf(ab[(size_t)j2 * CHID + tp] - cv, 0.f));
        h.w = f2tf32(fmaxf(ab[(size_t)j3 * CHID + tp] - cv, 0.f));
        *(uint4*)&hTu[tp * HS + kq * 4] = h;
    }
    __syncthreads();

    const int lane = tp & 31;
    const int w = tp >> 5;
    const int q = lane >> 2, kk = lane & 3;
    const uint4* Wt = (const uint4*)W2T;

    float d[2][4][4];
#pragma unroll
    for (int m = 0; m < 2; ++m)
#pragma unroll
        for (int n = 0; n < 4; ++n)
#pragma unroll
            for (int r = 0; r < 4; ++r) d[m][n][r] = 0.f;

    for (int kt = 0; kt < KT; ++kt) {
        const u32* col0 = hTu + (kt * 8 + kk) * HS;
        const u32* col4 = col0 + 4 * HS;
        u32 A0[4], A1[4];
        A0[0] = col0[q];       A0[1] = col0[q + 8];
        A0[2] = col4[q];       A0[3] = col4[q + 8];
        A1[0] = col0[16 + q];  A1[1] = col0[16 + q + 8];
        A1[2] = col4[16 + q];  A1[3] = col4[16 + q + 8];
        uint4 B0 = Wt[((kt * NW + w) * 32 + lane) * 2 + 0];
        uint4 B1 = Wt[((kt * NW + w) * 32 + lane) * 2 + 1];
        mma_tf32(d[0][0], A0, B0.x, B0.y);
        mma_tf32(d[0][1], A0, B0.z, B0.w);
        mma_tf32(d[0][2], A0, B1.x, B1.y);
        mma_tf32(d[0][3], A0, B1.z, B1.w);
        mma_tf32(d[1][0], A1, B0.x, B0.y);
        mma_tf32(d[1][1], A1, B0.z, B0.w);
        mma_tf32(d[1][2], A1, B1.x, B1.y);
        mma_tf32(d[1][3], A1, B1.z, B1.w);
    }

#pragma unroll
    for (int n = 0; n < 4; ++n) {
        float v0 = -FLT_MAX, v1 = -FLT_MAX;
#pragma unroll
        for (int m = 0; m < 2; ++m) {
            int r0 = m * 16 + q, r1 = r0 + 8;
            if (r0 < cnt) { v0 = fmaxf(v0, d[m][n][0]); v1 = fmaxf(v1, d[m][n][1]); }
            if (r1 < cnt) { v0 = fmaxf(v0, d[m][n][2]); v1 = fmaxf(v1, d[m][n][3]); }
        }
        v0 = fmaxf(v0, __shfl_xor_sync(0xffffffffu, v0, 4));
        v1 = fmaxf(v1, __shfl_xor_sync(0xffffffffu, v1, 4));
        v0 = fmaxf(v0, __shfl_xor_sync(0xffffffffu, v0, 8));
        v1 = fmaxf(v1, __shfl_xor_sync(0xffffffffu, v1, 8));
        v0 = fmaxf(v0, __shfl_xor_sync(0xffffffffu, v0, 16));
        v1 = fmaxf(v1, __shfl_xor_sync(0xffffffffu, v1, 16));
        if (lane < 4) {
            int c = w * 32 + n * 8 + lane * 2;
            float o0 = (cnt > 0) ? fmaxf(v0 + b2[c], 0.f) : 0.f;
            float o1 = (cnt > 0) ? fmaxf(v1 + b2[c + 1], 0.f) : 0.f;
            xout[((size_t)b * N + i) * COUT + c]     = o0;
            xout[((size_t)b * N + i) * COUT + c + 1] = o1;
        }
    }
}

// ---------------- head ----------------
__global__ void head_kernel(const float* __restrict__ x3,
                            const float* __restrict__ Wc1, const float* __restrict__ bc1,
                            const float* __restrict__ Wc2, const float* __restrict__ bc2,
                            const float* __restrict__ Wc3, const float* __restrict__ bc3,
                            const float* __restrict__ Wd1, const float* __restrict__ bd1,
                            const float* __restrict__ Wd2, const float* __restrict__ bd2,
                            float* __restrict__ out)
{
    __shared__ float sf[256], sh[256], sh2[256], slog[40], sd[2];
    const int b = blockIdx.x, t = threadIdx.x;

    float m = -FLT_MAX;
    for (int n = 0; n < N3; ++n)
        m = fmaxf(m, x3[((size_t)b * N3 + n) * 256 + t]);
    sf[t] = m;
    __syncthreads();

    float a = bc1[t];
    for (int c = 0; c < 256; ++c) a = fmaf(sf[c], Wc1[c * 256 + t], a);
    sh[t] = fmaxf(a, 0.f);
    __syncthreads();

    a = bc2[t];
    for (int c = 0; c < 256; ++c) a = fmaf(sh[c], Wc2[c * 256 + t], a);
    sh2[t] = fmaxf(a, 0.f);
    __syncthreads();

    if (t < 40) {
        float l = bc3[t];
        for (int c = 0; c < 256; ++c) l = fmaf(sh2[c], Wc3[c * 40 + t], l);
        slog[t] = l;
    }
    float a2 = bd1[t];
    for (int c = 0; c < 256; ++c) a2 = fmaf(sf[c], Wd1[c * 256 + t], a2);
    a2 = fmaxf(a2, 0.f);
    __syncthreads();
    sh[t] = a2;
    __syncthreads();
    if (t < 2) {
        float l = bd2[t];
        for (int c = 0; c < 256; ++c) l = fmaf(sh[c], Wd2[c * 2 + t], l);
        sd[t] = l;
    }
    __syncthreads();

    if (t < 40) {
        float mx = -FLT_MAX;
        for (int j = 0; j < 40; ++j) mx = fmaxf(mx, slog[j]);
        float se = 0.f;
        for (int j = 0; j < 40; ++j) se += expf(slog[j] - mx);
        out[b * 40 + t] = slog[t] - mx - logf(se);
    }
    if (t < 2) {
        float mx = fmaxf(sd[0], sd[1]);
        float se = expf(sd[0] - mx) + expf(sd[1] - mx);
        out[NB * 40 + b * 2 + t] = sd[t] - mx - logf(se);
    }
}

// ---------------- stream/event singletons ----------------
static cudaStream_t g_s2;
static cudaEvent_t g_evA, g_evP2, g_evP3;
static bool g_init = []() {
    cudaStreamCreateWithFlags(&g_s2, cudaStreamNonBlocking);
    cudaEventCreateWithFlags(&g_evA,  cudaEventDisableTiming);
    cudaEventCreateWithFlags(&g_evP2, cudaEventDisableTiming);
    cudaEventCreateWithFlags(&g_evP3, cudaEventDisableTiming);
    return true;
}();

// ---------------- launch ----------------
extern "C" void kernel_launch(void* const* d_in, const int* in_sizes, int n_in,
                              void* d_out, int out_size)
{
    const float* pos = (const float*)d_in[0];
    const float* W1a = (const float*)d_in[1];  const float* b1a = (const float*)d_in[2];
    const float* W1b = (const float*)d_in[3];  const float* b1b = (const float*)d_in[4];
    const float* W2a = (const float*)d_in[5];  const float* b2a = (const float*)d_in[6];
    const float* W2b = (const float*)d_in[7];  const float* b2b = (const float*)d_in[8];
    const float* W3a = (const float*)d_in[9];  const float* b3a = (const float*)d_in[10];
    const float* W3b = (const float*)d_in[11]; const float* b3b = (const float*)d_in[12];
    const float* Wc1 = (const float*)d_in[13]; const float* bc1 = (const float*)d_in[14];
    const float* Wc2 = (const float*)d_in[15]; const float* bc2 = (const float*)d_in[16];
    const float* Wc3 = (const float*)d_in[17]; const float* bc3 = (const float*)d_in[18];
    const float* Wd1 = (const float*)d_in[19]; const float* bd1 = (const float*)d_in[20];
    const float* Wd2 = (const float*)d_in[21]; const float* bd2 = (const float*)d_in[22];
    float* out = (float*)d_out;

    void *p_idx1, *p_cnt1, *p_a1, *p_x1, *p_fi1, *p_pos2, *p_x2g, *p_a2,
         *p_idx2, *p_cnt2, *p_x2, *p_fi2, *p_pos3, *p_x3g, *p_a3,
         *p_idx3, *p_cnt3, *p_x3, *p_pm1, *p_pm2, *p_pm3,
         *p_w1, *p_w2, *p_w3;
    cudaGetSymbolAddress(&p_idx1, g_idx1);
    cudaGetSymbolAddress(&p_cnt1, g_cnt1);
    cudaGetSymbolAddress(&p_a1,   g_a1);
    cudaGetSymbolAddress(&p_x1,   g_x1);
    cudaGetSymbolAddress(&p_fi1,  g_fi1);
    cudaGetSymbolAddress(&p_pos2, g_pos2);
    cudaGetSymbolAddress(&p_x2g,  g_x2g);
    cudaGetSymbolAddress(&p_a2,   g_a2);
    cudaGetSymbolAddress(&p_idx2, g_idx2);
    cudaGetSymbolAddress(&p_cnt2, g_cnt2);
    cudaGetSymbolAddress(&p_x2,   g_x2);
    cudaGetSymbolAddress(&p_fi2,  g_fi2);
    cudaGetSymbolAddress(&p_pos3, g_pos3);
    cudaGetSymbolAddress(&p_x3g,  g_x3g);
    cudaGetSymbolAddress(&p_a3,   g_a3);
    cudaGetSymbolAddress(&p_idx3, g_idx3);
    cudaGetSymbolAddress(&p_cnt3, g_cnt3);
    cudaGetSymbolAddress(&p_x3,   g_x3);
    cudaGetSymbolAddress(&p_pm1,  g_perm1);
    cudaGetSymbolAddress(&p_pm2,  g_perm2);
    cudaGetSymbolAddress(&p_pm3,  g_perm3);
    cudaGetSymbolAddress(&p_w1,   g_w2t1);
    cudaGetSymbolAddress(&p_w2,   g_w2t2);
    cudaGetSymbolAddress(&p_w3,   g_w2t3);

    const int smFps1 = N1 * 12 + 256;
    const int smFps2 = N2 * 12 + 256;
    const int smKnn  = 512 * 16;
    const int shc1 = 4 * (64 * 40 + 64)  * 4;
    const int shc2 = 2 * (128 * 40 + 128) * 4;
    const int shc3 = 1 * (256 * 40 + 256) * 4;
    cudaFuncSetAttribute(fps_kernel<8>,
                         cudaFuncAttributeMaxDynamicSharedMemorySize, 50176);

    const float r1 = 0.2f, r2 = 0.4f, r3 = 1.0f;

    // ======== fork at the very start: FPS spine on s2 (needs only pos) ====
    cudaEventRecord(g_evA, 0);
    cudaStreamWaitEvent(g_s2, g_evA, 0);
    fps_kernel<8><<<NB, 512, smFps1, g_s2>>>(pos, N2, (int*)p_fi1);
    posgather_kernel<<<(NB * N2 * 3 + 255) / 256, 256, 0, g_s2>>>(
        pos, (int*)p_fi1, (float*)p_pos2, N1, N2);
    cudaEventRecord(g_evP2, g_s2);
    fps_kernel<4><<<NB, 512, smFps2, g_s2>>>((float*)p_pos2, N3, (int*)p_fi2);
    posgather_kernel<<<(NB * N3 * 3 + 255) / 256, 256, 0, g_s2>>>(
        (float*)p_pos2, (int*)p_fi2, (float*)p_pos3, N2, N3);
    cudaEventRecord(g_evP3, g_s2);

    // ======== main stream: all compute ====================================
    // level 1
    binsort_kernel<5><<<NB, 256>>>(pos, N1, (int*)p_pm1);
    w2t_pre_kernel<64, 64><<<16, 256>>>(W1b, (u32*)p_w1);
    w2t_pre_kernel<128, 128><<<64, 256>>>(W2b, (u32*)p_w2);
    w2t_pre_kernel<256, 256><<<256, 256>>>(W3b, (u32*)p_w3);
    node_pre_kernel<0, 64><<<(NB * N1 * 64) / 256, 256>>>(
        nullptr, pos, W1a, b1a, (float*)p_a1, NB * N1);
    knn_kernel<<<(N1 / 512) * NB, 512, smKnn>>>(
        pos, N1, r1 * r1, (int*)p_idx1, (int*)p_cnt1, (int*)p_pm1);
    conv_mma_kernel<64, 64><<<dim3(N1 / 4, NB), 256, shc1>>>(
        (float*)p_a1, pos, (int*)p_idx1, (int*)p_cnt1,
        W1a, (u32*)p_w1, b1b, (float*)p_x1, N1);

    // level 2 (needs pos2/fi1 from s2)
    cudaStreamWaitEvent(0, g_evP2, 0);
    binsort_kernel<4><<<NB, 256>>>((float*)p_pos2, N2, (int*)p_pm2);
    knn_kernel<<<(N2 / 512) * NB, 512, smKnn>>>(
        (float*)p_pos2, N2, r2 * r2, (int*)p_idx2, (int*)p_cnt2, (int*)p_pm2);
    xgather_kernel<<<512, 256>>>((float*)p_x1, (int*)p_fi1,
                                 (float*)p_x2g, N1, N2, 64);
    node_pre_kernel<64, 128><<<(NB * N2 * 128) / 256, 256>>>(
        (float*)p_x2g, (float*)p_pos2, W2a, b2a, (float*)p_a2, NB * N2);
    conv_mma_kernel<128, 128><<<dim3(N2 / 2, NB), 256, shc2>>>(
        (float*)p_a2, (float*)p_pos2, (int*)p_idx2, (int*)p_cnt2,
        W2a + 64 * 128, (u32*)p_w2, b2b, (float*)p_x2, N2);

    // level 3 (needs pos3/fi2 from s2)
    cudaStreamWaitEvent(0, g_evP3, 0);
    binsort_kernel<4><<<NB, 256>>>((float*)p_pos3, N3, (int*)p_pm3);
    knn_kernel<<<(N3 / 512) * NB, 512, smKnn>>>(
        (float*)p_pos3, N3, r3 * r3, (int*)p_idx3, (int*)p_cnt3, (int*)p_pm3);
    xgather_kernel<<<512, 256>>>((float*)p_x2, (int*)p_fi2,
                                 (float*)p_x3g, N2, N3, 128);
    node_pre_kernel<128, 256><<<(NB * N3 * 256) / 256, 256>>>(
        (float*)p_x3g, (float*)p_pos3, W3a, b3a, (float*)p_a3, NB * N3);
    conv_mma_kernel<256, 256><<<dim3(N3, NB), 256, shc3>>>(
        (float*)p_a3, (float*)p_pos3, (int*)p_idx3, (int*)p_cnt3,
        W3a + 128 * 256, (u32*)p_w3, b3b, (float*)p_x3, N3);

    // head
    head_kernel<<<NB, 256>>>((float*)p_x3, Wc1, bc1, Wc2, bc2, Wc3, bc3,
                             Wd1, bd1, Wd2, bd2, out);

    (void)in_sizes; (void)n_in; (void)out_size; (void)g_init;
}